// round 14
// baseline (speedup 1.0000x reference)
#include <cuda_runtime.h>
#include <cuda_bf16.h>
#include <cstdint>

#define N_NODES  150000
#define N_EDGES  300000
#define N_GRAPHS 6000
#define HID      256

// ============================ helpers =======================================

__device__ __forceinline__ uint32_t smem_u32(const void* p) {
    uint32_t addr;
    asm("{ .reg .u64 tmp; cvta.to.shared.u64 tmp, %1; cvt.u32.u64 %0, tmp; }"
        : "=r"(addr) : "l"(p));
    return addr;
}

__device__ __forceinline__ void ldsm_x4(uint32_t addr, uint32_t* r) {
    asm volatile("ldmatrix.sync.aligned.m8n8.x4.shared.b16 {%0,%1,%2,%3}, [%4];"
                 : "=r"(r[0]), "=r"(r[1]), "=r"(r[2]), "=r"(r[3]) : "r"(addr));
}

__device__ __forceinline__ void mma16816(float* d, const uint32_t* a,
                                         uint32_t b0, uint32_t b1) {
    asm volatile(
        "mma.sync.aligned.m16n8k16.row.col.f32.bf16.bf16.f32 "
        "{%0,%1,%2,%3}, {%4,%5,%6,%7}, {%8,%9}, {%0,%1,%2,%3};"
        : "+f"(d[0]), "+f"(d[1]), "+f"(d[2]), "+f"(d[3])
        : "r"(a[0]), "r"(a[1]), "r"(a[2]), "r"(a[3]), "r"(b0), "r"(b1));
}

__device__ __forceinline__ void cp_async16(uint32_t smem_addr, const void* g) {
    asm volatile("cp.async.cg.shared.global [%0], [%1], 16;"
                 :: "r"(smem_addr), "l"(g));
}
#define CP_COMMIT() asm volatile("cp.async.commit_group;" ::: "memory")
#define CP_WAIT(n)  asm volatile("cp.async.wait_group %0;" :: "n"(n) : "memory")

__device__ __forceinline__ uint32_t pack_bf16x2(float a, float b) {
    __nv_bfloat16 ha = __float2bfloat16(a);
    __nv_bfloat16 hb = __float2bfloat16(b);
    return ((uint32_t)__bfloat16_as_ushort(hb) << 16) | __bfloat16_as_ushort(ha);
}

// PDL: programmatic dependent launch controls
__device__ __forceinline__ void pdl_trigger() {
    asm volatile("griddepcontrol.launch_dependents;");
}
__device__ __forceinline__ void pdl_wait() {
    asm volatile("griddepcontrol.wait;" ::: "memory");
}

// ============================ scratch buffers ===============================

__device__ __nv_bfloat16 g_A2hi[(size_t)N_NODES * HID];
__device__ __nv_bfloat16 g_A2lo[(size_t)N_NODES * HID];
__device__ float g_bufB[(size_t)N_NODES * HID];   // layer output h (gather src)
__device__ float g_bufC[(size_t)N_NODES * HID];   // scatter accumulator (init h)
__device__ float g_agg7[N_NODES * 7];
__device__ __nv_bfloat16 g_Whi[7 * HID * HID];    // weights, [N][K] bf16 hi
__device__ __nv_bfloat16 g_Wlo[7 * HID * HID];    // weights, [N][K] bf16 lo
__device__ float g_pooled[N_GRAPHS * HID];
__device__ float g_counts[N_GRAPHS];
__device__ float g_hid[N_GRAPHS * 128];

// ============================ small kernels =================================

__global__ void convert_weight_all(const float* __restrict__ W0,
                                   const float* __restrict__ W1,
                                   const float* __restrict__ W2,
                                   const float* __restrict__ W3,
                                   const float* __restrict__ W4,
                                   const float* __restrict__ W5,
                                   const float* __restrict__ W6,
                                   __nv_bfloat16* __restrict__ Whi,
                                   __nv_bfloat16* __restrict__ Wlo) {
    int w = blockIdx.y;
    const float* W = (w == 0) ? W0 : (w == 1) ? W1 : (w == 2) ? W2 :
                     (w == 3) ? W3 : (w == 4) ? W4 : (w == 5) ? W5 : W6;
    int n = blockIdx.x;   // 256
    int k = threadIdx.x;  // 256
    float v = W[k * HID + n];
    __nv_bfloat16 h = __float2bfloat16(v);
    size_t o = (size_t)w * HID * HID + n * HID + k;
    Whi[o] = h;
    Wlo[o] = __float2bfloat16(v - __bfloat162float(h));
}

__global__ void count_kernel(const int* __restrict__ batch,
                             float* __restrict__ counts) {
    int i = blockIdx.x * blockDim.x + threadIdx.x;
    if (i >= N_NODES) return;
    atomicAdd(&counts[batch[i]], 1.0f);
}

__global__ void scatter_add_7(const float* __restrict__ x,
                              const int* __restrict__ ei,
                              float* __restrict__ agg) {
    int e = blockIdx.x * blockDim.x + threadIdx.x;
    if (e >= N_EDGES) return;
    int s = ei[e];
    int d = ei[N_EDGES + e];
#pragma unroll
    for (int j = 0; j < 7; j++)
        atomicAdd(&agg[(size_t)d * 7 + j], x[(size_t)s * 7 + j]);
}

// scatter-add 256-dim: one warp per edge, PDL participant
__global__ void scatter_add_256(const float* __restrict__ x,
                                const int* __restrict__ ei,
                                float* __restrict__ agg) {
    int gw   = (blockIdx.x * blockDim.x + threadIdx.x) >> 5;
    int lane = threadIdx.x & 31;
    pdl_trigger();                 // allow next kernel to prefill weights
    if (gw >= N_EDGES) return;
    int s = ei[gw];                // edge list: independent of predecessor
    int d = ei[N_EDGES + gw];
    pdl_wait();                    // x (bufB) written by predecessor GEMM
    const float* xs = x + (size_t)s * HID;
    float* ad = agg + (size_t)d * HID;
#pragma unroll
    for (int j = 0; j < 8; j++)
        atomicAdd(ad + lane + 32 * j, xs[lane + 32 * j]);
}

// layer-1 first GEMM (K=7): 64 threads per node, 4 cols/thread
#define K7_BLOCKS 1184
__global__ void gemm_k7_relu_split(const float* __restrict__ A,
                                   const float* __restrict__ W,
                                   const float* __restrict__ bias,
                                   __nv_bfloat16* __restrict__ Chi,
                                   __nv_bfloat16* __restrict__ Clo) {
    const int grp = threadIdx.x >> 6;
    const int c4  = (threadIdx.x & 63) << 2;

    float w[7][4];
#pragma unroll
    for (int j = 0; j < 7; j++) {
        float4 wv = *reinterpret_cast<const float4*>(&W[j * HID + c4]);
        w[j][0] = wv.x; w[j][1] = wv.y; w[j][2] = wv.z; w[j][3] = wv.w;
    }
    float4 bv = *reinterpret_cast<const float4*>(&bias[c4]);
    float bi[4] = {bv.x, bv.y, bv.z, bv.w};

    for (int m = blockIdx.x * 4 + grp; m < N_NODES; m += K7_BLOCKS * 4) {
        const float* xr = A + (size_t)m * 7;
        float x0 = xr[0], x1 = xr[1], x2 = xr[2], x3 = xr[3];
        float x4 = xr[4], x5 = xr[5], x6 = xr[6];
        float acc[4];
#pragma unroll
        for (int i = 0; i < 4; i++) {
            float a = bi[i];
            a = fmaf(x0, w[0][i], a);
            a = fmaf(x1, w[1][i], a);
            a = fmaf(x2, w[2][i], a);
            a = fmaf(x3, w[3][i], a);
            a = fmaf(x4, w[4][i], a);
            a = fmaf(x5, w[5][i], a);
            a = fmaf(x6, w[6][i], a);
            acc[i] = fmaxf(a, 0.0f);
        }
        uint2 hp, lp;
        hp.x = pack_bf16x2(acc[0], acc[1]);
        hp.y = pack_bf16x2(acc[2], acc[3]);
        lp.x = pack_bf16x2(acc[0] - __bfloat162float(__float2bfloat16(acc[0])),
                           acc[1] - __bfloat162float(__float2bfloat16(acc[1])));
        lp.y = pack_bf16x2(acc[2] - __bfloat162float(__float2bfloat16(acc[2])),
                           acc[3] - __bfloat162float(__float2bfloat16(acc[3])));
        *reinterpret_cast<uint2*>(Chi + (size_t)m * HID + c4) = hp;
        *reinterpret_cast<uint2*>(Clo + (size_t)m * HID + c4) = lp;
    }
}

// =================== GEMM variant 1: bf16 A, swizzled 3-stage, PDL ==========
// mode 0: Cf (+Cc) fp32 out.  mode 1: Chi/Clo bf16 split out.
// mode 2: atomic mean-pool accumulate into pooled[batch[r]*256+col].

#define TILE_SW  8192
#define STAGE_SW (4 * TILE_SW)
#define GEMM_SMEM (3 * STAGE_SW)

__device__ __forceinline__ uint32_t swz(int row, uint32_t kcol) {
    return (uint32_t)(row * 64) + (((kcol ^ ((uint32_t)(row >> 1) & 3u)) << 4));
}

__global__ __launch_bounds__(256, 2)
void mma_gemm_split(int M,
                    const uint4* __restrict__ Ahi4, const uint4* __restrict__ Alo4,
                    const uint4* __restrict__ Bhi4, const uint4* __restrict__ Blo4,
                    const float* __restrict__ bias,
                    float* __restrict__ Cf, float* __restrict__ Cc,
                    __nv_bfloat16* __restrict__ Chi,
                    __nv_bfloat16* __restrict__ Clo,
                    const int* __restrict__ batch,
                    float* __restrict__ pooled,
                    int mode) {
    extern __shared__ char smem[];
    const uint32_t sb = smem_u32(smem);

    const int tid  = threadIdx.x;
    const int wid  = tid >> 5;
    const int lane = tid & 31;
    const int wm   = wid & 1;
    const int wn   = wid >> 1;
    const int block_col = blockIdx.x * 128;
    const int block_row = blockIdx.y * 128;

    const int a_lrow = lane & 15;
    const int a_lcol = (lane >> 4) << 3;
    const int b_lrow = (lane & 7) + ((lane >> 4) & 1) * 8;
    const int b_lcol = ((lane >> 3) & 1) << 3;
    const uint32_t a_k0 = (uint32_t)(a_lcol >> 3);
    const uint32_t b_k0 = (uint32_t)(b_lcol >> 3);

    uint32_t a_rowoff[4], b_rowoff[2];
    uint32_t a_s[4], b_s[2];
#pragma unroll
    for (int f = 0; f < 4; f++) {
        int r = wm * 64 + f * 16 + a_lrow;
        a_rowoff[f] = (uint32_t)(r * 64);
        a_s[f] = (uint32_t)(r >> 1) & 3u;
    }
#pragma unroll
    for (int p = 0; p < 2; p++) {
        int r = wn * 32 + p * 16 + b_lrow;
        b_rowoff[p] = (uint32_t)(r * 64);
        b_s[p] = (uint32_t)(r >> 1) & 3u;
    }

    float acc[4][4][4];
#pragma unroll
    for (int i = 0; i < 4; i++)
#pragma unroll
        for (int j = 0; j < 4; j++)
#pragma unroll
            for (int c = 0; c < 4; c++) acc[i][j][c] = 0.0f;

    const int ldrow = tid >> 2;
    const int ldc   = tid & 3;

    auto issueB = [&](int kc) {
        uint32_t sbase = sb + (uint32_t)(kc % 3) * STAGE_SW;
#pragma unroll
        for (int h = 0; h < 2; h++) {
            int row = ldrow + h * 64;
            size_t gB = (size_t)(block_col + row) * 32 + kc * 4 + ldc;
            uint32_t so = swz(row, (uint32_t)ldc);
            cp_async16(sbase + 2 * TILE_SW + so, Bhi4 + gB);
            cp_async16(sbase + 3 * TILE_SW + so, Blo4 + gB);
        }
    };
    auto issueA = [&](int kc) {
        uint32_t sbase = sb + (uint32_t)(kc % 3) * STAGE_SW;
#pragma unroll
        for (int h = 0; h < 2; h++) {
            int row = ldrow + h * 64;
            int rg = block_row + row;
            if (rg >= M) rg = M - 1;
            size_t gA = (size_t)rg * 32 + kc * 4 + ldc;
            uint32_t so = swz(row, (uint32_t)ldc);
            cp_async16(sbase + 0 * TILE_SW + so, Ahi4 + gA);
            cp_async16(sbase + 1 * TILE_SW + so, Alo4 + gA);
        }
    };

    // PDL prologue: weights first (independent), then wait, then A.
    issueB(0);
    issueB(1);
    pdl_wait();
    issueA(0); CP_COMMIT();       // group 0 = {B0, B1, A0}
    issueA(1); CP_COMMIT();       // group 1 = {A1}

    for (int kc = 0; kc < 8; kc++) {
        CP_WAIT(1);
        __syncthreads();
        if (kc < 6) { issueA(kc + 2); issueB(kc + 2); CP_COMMIT(); }

        uint32_t base = sb + (uint32_t)(kc % 3) * STAGE_SW;
        uint32_t uAhi = base + 0 * TILE_SW;
        uint32_t uAlo = base + 1 * TILE_SW;
        uint32_t uBhi = base + 2 * TILE_SW;
        uint32_t uBlo = base + 3 * TILE_SW;

        uint32_t ah[4][4], al[4][4], bh[2][4], bl[2][4];
#pragma unroll
        for (int ks16 = 0; ks16 < 2; ks16++) {
            const uint32_t kb = (uint32_t)(ks16 * 2);
#pragma unroll
            for (int f = 0; f < 4; f++) {
                uint32_t off = a_rowoff[f] + (((a_k0 + kb) ^ a_s[f]) << 4);
                ldsm_x4(uAhi + off, ah[f]);
                ldsm_x4(uAlo + off, al[f]);
            }
#pragma unroll
            for (int p = 0; p < 2; p++) {
                uint32_t off = b_rowoff[p] + (((b_k0 + kb) ^ b_s[p]) << 4);
                ldsm_x4(uBhi + off, bh[p]);
                ldsm_x4(uBlo + off, bl[p]);
            }
#pragma unroll
            for (int mf = 0; mf < 4; mf++)
#pragma unroll
                for (int nf = 0; nf < 4; nf++) {
                    int p = nf >> 1, q = (nf & 1) * 2;
                    mma16816(acc[mf][nf], ah[mf], bh[p][q], bh[p][q + 1]);
                    mma16816(acc[mf][nf], ah[mf], bl[p][q], bl[p][q + 1]);
                    mma16816(acc[mf][nf], al[mf], bh[p][q], bh[p][q + 1]);
                }
        }
    }

    pdl_trigger();   // mainloop done: successor may launch during epilogue

    // ---- epilogue ----
#pragma unroll
    for (int mf = 0; mf < 4; mf++) {
        int r0 = block_row + wm * 64 + mf * 16 + (lane >> 2);
        int r1 = r0 + 8;
#pragma unroll
        for (int nf = 0; nf < 4; nf++) {
            int col = block_col + wn * 32 + nf * 8 + (lane & 3) * 2;
            float b0 = bias[col], b1 = bias[col + 1];
            float v00 = fmaxf(acc[mf][nf][0] + b0, 0.f);
            float v01 = fmaxf(acc[mf][nf][1] + b1, 0.f);
            float v10 = fmaxf(acc[mf][nf][2] + b0, 0.f);
            float v11 = fmaxf(acc[mf][nf][3] + b1, 0.f);
            if (mode == 0) {
                if (r0 < M) {
                    *reinterpret_cast<float2*>(&Cf[(size_t)r0 * HID + col]) =
                        make_float2(v00, v01);
                    *reinterpret_cast<float2*>(&Cc[(size_t)r0 * HID + col]) =
                        make_float2(v00, v01);
                }
                if (r1 < M) {
                    *reinterpret_cast<float2*>(&Cf[(size_t)r1 * HID + col]) =
                        make_float2(v10, v11);
                    *reinterpret_cast<float2*>(&Cc[(size_t)r1 * HID + col]) =
                        make_float2(v10, v11);
                }
            } else if (mode == 1) {
                uint32_t hp0 = pack_bf16x2(v00, v01);
                uint32_t hp1 = pack_bf16x2(v10, v11);
                float w00 = v00 - __bfloat162float(__float2bfloat16(v00));
                float w01 = v01 - __bfloat162float(__float2bfloat16(v01));
                float w10 = v10 - __bfloat162float(__float2bfloat16(v10));
                float w11 = v11 - __bfloat162float(__float2bfloat16(v11));
                uint32_t lp0 = pack_bf16x2(w00, w01);
                uint32_t lp1 = pack_bf16x2(w10, w11);
                if (r0 < M) {
                    *reinterpret_cast<uint32_t*>(Chi + (size_t)r0 * HID + col) = hp0;
                    *reinterpret_cast<uint32_t*>(Clo + (size_t)r0 * HID + col) = lp0;
                }
                if (r1 < M) {
                    *reinterpret_cast<uint32_t*>(Chi + (size_t)r1 * HID + col) = hp1;
                    *reinterpret_cast<uint32_t*>(Clo + (size_t)r1 * HID + col) = lp1;
                }
            } else {
                if (r0 < M) {
                    float* pd = pooled + (size_t)batch[r0] * HID + col;
                    atomicAdd(pd + 0, v00);
                    atomicAdd(pd + 1, v01);
                }
                if (r1 < M) {
                    float* pd = pooled + (size_t)batch[r1] * HID + col;
                    atomicAdd(pd + 0, v10);
                    atomicAdd(pd + 1, v11);
                }
            }
        }
    }
}

// =================== GEMM variant 2: fp32 A, in-kernel split, PDL ===========

#define F_A32_STG 16384
#define F_B_OFF   (3 * F_A32_STG)
#define F_B_STG   (2 * TILE_SW)
#define F_AHI     (F_B_OFF + 3 * F_B_STG)
#define F_ALO     (F_AHI + TILE_SW)
#define F_SMEM    (F_ALO + TILE_SW)

__global__ __launch_bounds__(256, 2)
void mma_gemm_split_f32a(int M,
                         const float* __restrict__ Af,
                         const uint4* __restrict__ Bhi4,
                         const uint4* __restrict__ Blo4,
                         const float* __restrict__ bias,
                         __nv_bfloat16* __restrict__ Chi,
                         __nv_bfloat16* __restrict__ Clo) {
    extern __shared__ char smem[];
    const uint32_t sb = smem_u32(smem);

    const int tid  = threadIdx.x;
    const int wid  = tid >> 5;
    const int lane = tid & 31;
    const int wm   = wid & 1;
    const int wn   = wid >> 1;
    const int block_col = blockIdx.x * 128;
    const int block_row = blockIdx.y * 128;

    const int a_lrow = lane & 15;
    const int a_lcol = (lane >> 4) << 3;
    const int b_lrow = (lane & 7) + ((lane >> 4) & 1) * 8;
    const int b_lcol = ((lane >> 3) & 1) << 3;
    const uint32_t a_k0 = (uint32_t)(a_lcol >> 3);
    const uint32_t b_k0 = (uint32_t)(b_lcol >> 3);

    uint32_t a_rowoff[4], b_rowoff[2];
    uint32_t a_s[4], b_s[2];
#pragma unroll
    for (int f = 0; f < 4; f++) {
        int r = wm * 64 + f * 16 + a_lrow;
        a_rowoff[f] = (uint32_t)(r * 64);
        a_s[f] = (uint32_t)(r >> 1) & 3u;
    }
#pragma unroll
    for (int p = 0; p < 2; p++) {
        int r = wn * 32 + p * 16 + b_lrow;
        b_rowoff[p] = (uint32_t)(r * 64);
        b_s[p] = (uint32_t)(r >> 1) & 3u;
    }

    float acc[4][4][4];
#pragma unroll
    for (int i = 0; i < 4; i++)
#pragma unroll
        for (int j = 0; j < 4; j++)
#pragma unroll
            for (int c = 0; c < 4; c++) acc[i][j][c] = 0.0f;

    const int ldrow = tid >> 2;
    const int ldc   = tid & 3;
    const int crow  = tid >> 1;
    const int chalf = tid & 1;

    auto issueB = [&](int kc) {
        uint32_t bbase = sb + F_B_OFF + (uint32_t)(kc % 3) * F_B_STG;
#pragma unroll
        for (int h = 0; h < 2; h++) {
            int row = ldrow + h * 64;
            size_t gB = (size_t)(block_col + row) * 32 + kc * 4 + ldc;
            uint32_t so = swz(row, (uint32_t)ldc);
            cp_async16(bbase + so, Bhi4 + gB);
            cp_async16(bbase + TILE_SW + so, Blo4 + gB);
        }
    };
    auto issueA = [&](int kc) {
        int s = kc % 3;
#pragma unroll
        for (int i = 0; i < 4; i++) {
            int idx = tid + i * 256;
            int row = idx >> 3, c = idx & 7;
            int rg = block_row + row;
            if (rg >= M) rg = M - 1;
            const float* g = Af + (size_t)rg * 256 + kc * 32 + c * 4;
            uint32_t so = (uint32_t)(row * 128) +
                          (((uint32_t)(c ^ (row & 7))) << 4);
            cp_async16(sb + (uint32_t)(s * F_A32_STG) + so, g);
        }
    };

    issueB(0);
    issueB(1);
    pdl_wait();
    issueA(0); CP_COMMIT();
    issueA(1); CP_COMMIT();

    for (int kc = 0; kc < 8; kc++) {
        CP_WAIT(1);
        __syncthreads();
        if (kc < 6) { issueA(kc + 2); issueB(kc + 2); CP_COMMIT(); }

        {
            const char* afb = smem + (kc % 3) * F_A32_STG + crow * 128;
            uint32_t rs = (uint32_t)(crow & 7);
            float4 v0 = *reinterpret_cast<const float4*>(
                afb + (((uint32_t)(chalf * 4 + 0) ^ rs) << 4));
            float4 v1 = *reinterpret_cast<const float4*>(
                afb + (((uint32_t)(chalf * 4 + 1) ^ rs) << 4));
            float4 v2 = *reinterpret_cast<const float4*>(
                afb + (((uint32_t)(chalf * 4 + 2) ^ rs) << 4));
            float4 v3 = *reinterpret_cast<const float4*>(
                afb + (((uint32_t)(chalf * 4 + 3) ^ rs) << 4));
            uint4 H0, H1, L0, L1;
            H0.x = pack_bf16x2(v0.x, v0.y); H0.y = pack_bf16x2(v0.z, v0.w);
            H0.z = pack_bf16x2(v1.x, v1.y); H0.w = pack_bf16x2(v1.z, v1.w);
            H1.x = pack_bf16x2(v2.x, v2.y); H1.y = pack_bf16x2(v2.z, v2.w);
            H1.z = pack_bf16x2(v3.x, v3.y); H1.w = pack_bf16x2(v3.z, v3.w);
            L0.x = pack_bf16x2(v0.x - __bfloat162float(__float2bfloat16(v0.x)),
                               v0.y - __bfloat162float(__float2bfloat16(v0.y)));
            L0.y = pack_bf16x2(v0.z - __bfloat162float(__float2bfloat16(v0.z)),
                               v0.w - __bfloat162float(__float2bfloat16(v0.w)));
            L0.z = pack_bf16x2(v1.x - __bfloat162float(__float2bfloat16(v1.x)),
                               v1.y - __bfloat162float(__float2bfloat16(v1.y)));
            L0.w = pack_bf16x2(v1.z - __bfloat162float(__float2bfloat16(v1.z)),
                               v1.w - __bfloat162float(__float2bfloat16(v1.w)));
            L1.x = pack_bf16x2(v2.x - __bfloat162float(__float2bfloat16(v2.x)),
                               v2.y - __bfloat162float(__float2bfloat16(v2.y)));
            L1.y = pack_bf16x2(v2.z - __bfloat162float(__float2bfloat16(v2.z)),
                               v2.w - __bfloat162float(__float2bfloat16(v2.w)));
            L1.z = pack_bf16x2(v3.x - __bfloat162float(__float2bfloat16(v3.x)),
                               v3.y - __bfloat162float(__float2bfloat16(v3.y)));
            L1.w = pack_bf16x2(v3.z - __bfloat162float(__float2bfloat16(v3.z)),
                               v3.w - __bfloat162float(__float2bfloat16(v3.w)));
            uint32_t cs = (uint32_t)(crow >> 1) & 3u;
            uint32_t g0 = ((uint32_t)(chalf * 2 + 0) ^ cs) << 4;
            uint32_t g1 = ((uint32_t)(chalf * 2 + 1) ^ cs) << 4;
            char* ah = smem + F_AHI + crow * 64;
            char* al = smem + F_ALO + crow * 64;
            *reinterpret_cast<uint4*>(ah + g0) = H0;
            *reinterpret_cast<uint4*>(ah + g1) = H1;
            *reinterpret_cast<uint4*>(al + g0) = L0;
            *reinterpret_cast<uint4*>(al + g1) = L1;
        }
        __syncthreads();

        uint32_t uAhi = sb + F_AHI;
        uint32_t uAlo = sb + F_ALO;
        uint32_t uBhi = sb + F_B_OFF + (uint32_t)(kc % 3) * F_B_STG;
        uint32_t uBlo = uBhi + TILE_SW;

        uint32_t ah[4][4], al[4][4], bh[2][4], bl[2][4];
#pragma unroll
        for (int ks16 = 0; ks16 < 2; ks16++) {
            const uint32_t kb = (uint32_t)(ks16 * 2);
#pragma unroll
            for (int f = 0; f < 4; f++) {
                uint32_t off = a_rowoff[f] + (((a_k0 + kb) ^ a_s[f]) << 4);
                ldsm_x4(uAhi + off, ah[f]);
                ldsm_x4(uAlo + off, al[f]);
            }
#pragma unroll
            for (int p = 0; p < 2; p++) {
                uint32_t off = b_rowoff[p] + (((b_k0 + kb) ^ b_s[p]) << 4);
                ldsm_x4(uBhi + off, bh[p]);
                ldsm_x4(uBlo + off, bl[p]);
            }
#pragma unroll
            for (int mf = 0; mf < 4; mf++)
#pragma unroll
                for (int nf = 0; nf < 4; nf++) {
                    int p = nf >> 1, q = (nf & 1) * 2;
                    mma16816(acc[mf][nf], ah[mf], bh[p][q], bh[p][q + 1]);
                    mma16816(acc[mf][nf], ah[mf], bl[p][q], bl[p][q + 1]);
                    mma16816(acc[mf][nf], al[mf], bh[p][q], bh[p][q + 1]);
                }
        }
    }

    pdl_trigger();

#pragma unroll
    for (int mf = 0; mf < 4; mf++) {
        int r0 = block_row + wm * 64 + mf * 16 + (lane >> 2);
        int r1 = r0 + 8;
#pragma unroll
        for (int nf = 0; nf < 4; nf++) {
            int col = block_col + wn * 32 + nf * 8 + (lane & 3) * 2;
            float b0 = bias[col], b1 = bias[col + 1];
            float v00 = fmaxf(acc[mf][nf][0] + b0, 0.f);
            float v01 = fmaxf(acc[mf][nf][1] + b1, 0.f);
            float v10 = fmaxf(acc[mf][nf][2] + b0, 0.f);
            float v11 = fmaxf(acc[mf][nf][3] + b1, 0.f);
            uint32_t hp0 = pack_bf16x2(v00, v01);
            uint32_t hp1 = pack_bf16x2(v10, v11);
            float w00 = v00 - __bfloat162float(__float2bfloat16(v00));
            float w01 = v01 - __bfloat162float(__float2bfloat16(v01));
            float w10 = v10 - __bfloat162float(__float2bfloat16(v10));
            float w11 = v11 - __bfloat162float(__float2bfloat16(v11));
            uint32_t lp0 = pack_bf16x2(w00, w01);
            uint32_t lp1 = pack_bf16x2(w10, w11);
            if (r0 < M) {
                *reinterpret_cast<uint32_t*>(Chi + (size_t)r0 * HID + col) = hp0;
                *reinterpret_cast<uint32_t*>(Clo + (size_t)r0 * HID + col) = lp0;
            }
            if (r1 < M) {
                *reinterpret_cast<uint32_t*>(Chi + (size_t)r1 * HID + col) = hp1;
                *reinterpret_cast<uint32_t*>(Clo + (size_t)r1 * HID + col) = lp1;
            }
        }
    }
}

// ====== fp32 tiled SGEMM (head GEMM) with fused mean-divide =================

__global__ __launch_bounds__(256)
void sgemm_bias_relu(int M, const float* __restrict__ A,
                     const float* __restrict__ B,
                     const float* __restrict__ bias,
                     float* __restrict__ C,
                     int N, int K, int doRelu,
                     const float* __restrict__ rowdiv) {
    __shared__ float As[8][128];
    __shared__ float Bs[8][128];

    const int tid       = threadIdx.x;
    const int block_row = blockIdx.y * 128;
    const int block_col = blockIdx.x * 128;

    const int aRow = tid >> 1;
    const int aCol = (tid & 1) << 2;
    const int bRow = tid >> 5;
    const int bCol = (tid & 31) << 2;
    const int trow = (tid >> 4) << 3;
    const int tcol = (tid & 15) << 3;

    float rdiv = 1.0f;
    if (rowdiv && block_row + aRow < M)
        rdiv = 1.0f / fmaxf(rowdiv[block_row + aRow], 1.0f);

    float acc[8][8];
#pragma unroll
    for (int i = 0; i < 8; i++)
#pragma unroll
        for (int j = 0; j < 8; j++) acc[i][j] = 0.0f;

    for (int kt = 0; kt < K; kt += 8) {
        float4 av = make_float4(0.f, 0.f, 0.f, 0.f);
        if (block_row + aRow < M)
            av = *reinterpret_cast<const float4*>(&A[(size_t)(block_row + aRow) * K + kt + aCol]);
        As[aCol + 0][aRow] = av.x * rdiv;
        As[aCol + 1][aRow] = av.y * rdiv;
        As[aCol + 2][aRow] = av.z * rdiv;
        As[aCol + 3][aRow] = av.w * rdiv;

        float4 bv = *reinterpret_cast<const float4*>(&B[(size_t)(kt + bRow) * N + block_col + bCol]);
        *reinterpret_cast<float4*>(&Bs[bRow][bCol]) = bv;
        __syncthreads();

#pragma unroll
        for (int k = 0; k < 8; k++) {
            float ra[8], rb[8];
#pragma unroll
            for (int i = 0; i < 8; i++) ra[i] = As[k][trow + i];
#pragma unroll
            for (int j = 0; j < 8; j++) rb[j] = Bs[k][tcol + j];
#pragma unroll
            for (int i = 0; i < 8; i++)
#pragma unroll
                for (int j = 0; j < 8; j++)
                    acc[i][j] = fmaf(ra[i], rb[j], acc[i][j]);
        }
        __syncthreads();
    }

#pragma unroll
    for (int i = 0; i < 8; i++) {
        int r = block_row + trow + i;
        if (r < M) {
#pragma unroll
            for (int j = 0; j < 8; j += 4) {
                float4 v;
                v.x = acc[i][j + 0] + bias[block_col + tcol + j + 0];
                v.y = acc[i][j + 1] + bias[block_col + tcol + j + 1];
                v.z = acc[i][j + 2] + bias[block_col + tcol + j + 2];
                v.w = acc[i][j + 3] + bias[block_col + tcol + j + 3];
                if (doRelu) {
                    v.x = fmaxf(v.x, 0.f); v.y = fmaxf(v.y, 0.f);
                    v.z = fmaxf(v.z, 0.f); v.w = fmaxf(v.w, 0.f);
                }
                *reinterpret_cast<float4*>(&C[(size_t)r * N + block_col + tcol + j]) = v;
            }
        }
    }
}

// ============================ head final ====================================

__global__ void head_final(const float* __restrict__ hid,
                           const float* __restrict__ W,
                           const float* __restrict__ b,
                           float* __restrict__ out) {
    int m = blockIdx.x * blockDim.x + threadIdx.x;
    if (m >= N_GRAPHS) return;
    float a0 = b[0], a1 = b[1], a2 = b[2];
    const float* hs = hid + (size_t)m * 128;
#pragma unroll 8
    for (int k = 0; k < 128; k++) {
        float h = hs[k];
        a0 = fmaf(h, W[k * 3 + 0], a0);
        a1 = fmaf(h, W[k * 3 + 1], a1);
        a2 = fmaf(h, W[k * 3 + 2], a2);
    }
    out[m * 3 + 0] = a0;
    out[m * 3 + 1] = a1;
    out[m * 3 + 2] = a2;
}

// ============================ launch ========================================

template <typename F, typename... Args>
static void launch_pdl(F* kernel, dim3 grid, dim3 block, size_t smem,
                       Args... args) {
    cudaLaunchConfig_t cfg = {};
    cfg.gridDim = grid;
    cfg.blockDim = block;
    cfg.dynamicSmemBytes = smem;
    cfg.stream = 0;
    cudaLaunchAttribute attr[1];
    attr[0].id = cudaLaunchAttributeProgrammaticStreamSerialization;
    attr[0].val.programmaticStreamSerializationAllowed = 1;
    cfg.attrs = attr;
    cfg.numAttrs = 1;
    cudaLaunchKernelEx(&cfg, kernel, args...);
}

extern "C" void kernel_launch(void* const* d_in, const int* in_sizes, int n_in,
                              void* d_out, int out_size) {
    const float* x     = (const float*)d_in[0];
    const int*   ei    = (const int*)d_in[1];
    const int*   batch = (const int*)d_in[2];

    const float* Wa[4], *ba[4], *Wb[4], *bb[4];
    for (int l = 0; l < 4; l++) {
        Wa[l] = (const float*)d_in[3 + 4 * l + 0];
        ba[l] = (const float*)d_in[3 + 4 * l + 1];
        Wb[l] = (const float*)d_in[3 + 4 * l + 2];
        bb[l] = (const float*)d_in[3 + 4 * l + 3];
    }
    const float* Wh1 = (const float*)d_in[19];
    const float* bh1 = (const float*)d_in[20];
    const float* Wh2 = (const float*)d_in[21];
    const float* bh2 = (const float*)d_in[22];
    float* out = (float*)d_out;

    __nv_bfloat16 *A2hi, *A2lo, *Whi, *Wlo;
    float *bufB, *bufC, *agg7, *pooled, *counts, *hid;
    cudaGetSymbolAddress((void**)&A2hi,   g_A2hi);
    cudaGetSymbolAddress((void**)&A2lo,   g_A2lo);
    cudaGetSymbolAddress((void**)&Whi,    g_Whi);
    cudaGetSymbolAddress((void**)&Wlo,    g_Wlo);
    cudaGetSymbolAddress((void**)&bufB,   g_bufB);
    cudaGetSymbolAddress((void**)&bufC,   g_bufC);
    cudaGetSymbolAddress((void**)&agg7,   g_agg7);
    cudaGetSymbolAddress((void**)&pooled, g_pooled);
    cudaGetSymbolAddress((void**)&counts, g_counts);
    cudaGetSymbolAddress((void**)&hid,    g_hid);

    cudaFuncSetAttribute(mma_gemm_split,
                         cudaFuncAttributeMaxDynamicSharedMemorySize, GEMM_SMEM);
    cudaFuncSetAttribute(mma_gemm_split_f32a,
                         cudaFuncAttributeMaxDynamicSharedMemorySize, F_SMEM);

    // ---- prologue: weights, counts, pooled init ----
    dim3 cw_grid(HID, 7);
    convert_weight_all<<<cw_grid, HID>>>(Wb[0], Wa[1], Wb[1], Wa[2], Wb[2],
                                         Wa[3], Wb[3], Whi, Wlo);
    cudaMemsetAsync(pooled, 0, (size_t)N_GRAPHS * HID * sizeof(float));
    cudaMemsetAsync(counts, 0, (size_t)N_GRAPHS * sizeof(float));
    count_kernel<<<(N_NODES + 255) / 256, 256>>>(batch, counts);

    dim3 mma_grid(2, (N_NODES + 127) / 128);
    dim3 sc_grid((unsigned)(((size_t)N_EDGES * 32 + 255) / 256));

    // ---- layer 1 ----
    cudaMemcpyAsync(agg7, x, (size_t)N_NODES * 7 * sizeof(float),
                    cudaMemcpyDeviceToDevice);
    scatter_add_7<<<(N_EDGES + 255) / 256, 256>>>(x, ei, agg7);
    gemm_k7_relu_split<<<K7_BLOCKS, 256>>>(agg7, Wa[0], ba[0], A2hi, A2lo);
    launch_pdl(mma_gemm_split, mma_grid, dim3(256), (size_t)GEMM_SMEM,
               N_NODES, (const uint4*)A2hi, (const uint4*)A2lo,
               (const uint4*)Whi, (const uint4*)Wlo,
               bb[0], bufB, bufC, (__nv_bfloat16*)nullptr,
               (__nv_bfloat16*)nullptr, (const int*)nullptr,
               (float*)nullptr, 0);

    // ---- layers 2..4 ----
    for (int l = 1; l < 4; l++) {
        launch_pdl(scatter_add_256, sc_grid, dim3(256), (size_t)0,
                   (const float*)bufB, ei, bufC);
        launch_pdl(mma_gemm_split_f32a, mma_grid, dim3(256), (size_t)F_SMEM,
                   N_NODES, (const float*)bufC,
                   (const uint4*)(Whi + (size_t)(2 * l - 1) * HID * HID),
                   (const uint4*)(Wlo + (size_t)(2 * l - 1) * HID * HID),
                   ba[l], A2hi, A2lo);
        if (l < 3) {
            launch_pdl(mma_gemm_split, mma_grid, dim3(256), (size_t)GEMM_SMEM,
                       N_NODES, (const uint4*)A2hi, (const uint4*)A2lo,
                       (const uint4*)(Whi + (size_t)(2 * l) * HID * HID),
                       (const uint4*)(Wlo + (size_t)(2 * l) * HID * HID),
                       bb[l], bufB, bufC, (__nv_bfloat16*)nullptr,
                       (__nv_bfloat16*)nullptr, (const int*)nullptr,
                       (float*)nullptr, 0);
        } else {
            launch_pdl(mma_gemm_split, mma_grid, dim3(256), (size_t)GEMM_SMEM,
                       N_NODES, (const uint4*)A2hi, (const uint4*)A2lo,
                       (const uint4*)(Whi + (size_t)(2 * l) * HID * HID),
                       (const uint4*)(Wlo + (size_t)(2 * l) * HID * HID),
                       bb[l], (float*)nullptr, (float*)nullptr,
                       (__nv_bfloat16*)nullptr, (__nv_bfloat16*)nullptr,
                       batch, pooled, 2);
        }
    }

    // ---- head (mean-divide fused into A load) ----
    dim3 head_grid(1, (N_GRAPHS + 127) / 128);
    sgemm_bias_relu<<<head_grid, 256>>>(N_GRAPHS, pooled, Wh1, bh1, hid,
                                        128, 256, 1, counts);
    head_final<<<(N_GRAPHS + 255) / 256, 256>>>(hid, Wh2, bh2, out);
}

// round 15
// speedup vs baseline: 1.1641x; 1.1641x over previous
#include <cuda_runtime.h>
#include <cuda_bf16.h>
#include <cstdint>

#define N_NODES  150000
#define N_EDGES  300000
#define N_GRAPHS 6000
#define HID      256

// ============================ helpers =======================================

__device__ __forceinline__ uint32_t smem_u32(const void* p) {
    uint32_t addr;
    asm("{ .reg .u64 tmp; cvta.to.shared.u64 tmp, %1; cvt.u32.u64 %0, tmp; }"
        : "=r"(addr) : "l"(p));
    return addr;
}

__device__ __forceinline__ void ldsm_x4(uint32_t addr, uint32_t* r) {
    asm volatile("ldmatrix.sync.aligned.m8n8.x4.shared.b16 {%0,%1,%2,%3}, [%4];"
                 : "=r"(r[0]), "=r"(r[1]), "=r"(r[2]), "=r"(r[3]) : "r"(addr));
}

__device__ __forceinline__ void mma16816(float* d, const uint32_t* a,
                                         uint32_t b0, uint32_t b1) {
    asm volatile(
        "mma.sync.aligned.m16n8k16.row.col.f32.bf16.bf16.f32 "
        "{%0,%1,%2,%3}, {%4,%5,%6,%7}, {%8,%9}, {%0,%1,%2,%3};"
        : "+f"(d[0]), "+f"(d[1]), "+f"(d[2]), "+f"(d[3])
        : "r"(a[0]), "r"(a[1]), "r"(a[2]), "r"(a[3]), "r"(b0), "r"(b1));
}

__device__ __forceinline__ void cp_async16(uint32_t smem_addr, const void* g) {
    asm volatile("cp.async.cg.shared.global [%0], [%1], 16;"
                 :: "r"(smem_addr), "l"(g));
}
#define CP_COMMIT() asm volatile("cp.async.commit_group;" ::: "memory")
#define CP_WAIT(n)  asm volatile("cp.async.wait_group %0;" :: "n"(n) : "memory")

__device__ __forceinline__ uint32_t pack_bf16x2(float a, float b) {
    __nv_bfloat16 ha = __float2bfloat16(a);
    __nv_bfloat16 hb = __float2bfloat16(b);
    return ((uint32_t)__bfloat16_as_ushort(hb) << 16) | __bfloat16_as_ushort(ha);
}

__device__ __forceinline__ void pdl_trigger() {
    asm volatile("griddepcontrol.launch_dependents;");
}
__device__ __forceinline__ void pdl_wait() {
    asm volatile("griddepcontrol.wait;" ::: "memory");
}

// ============================ scratch buffers ===============================

__device__ __nv_bfloat16 g_A2hi[(size_t)N_NODES * HID];
__device__ __nv_bfloat16 g_A2lo[(size_t)N_NODES * HID];
__device__ float g_bufB[(size_t)N_NODES * HID];   // layer output h (gather src)
__device__ float g_bufC[(size_t)N_NODES * HID];   // scatter accumulator (init h)
__device__ float g_agg7[N_NODES * 7];
__device__ __nv_bfloat16 g_Whi[7 * HID * HID];    // weights, [N][K] bf16 hi
__device__ float g_pooled[N_GRAPHS * HID];
__device__ float g_counts[N_GRAPHS];
__device__ float g_hid[N_GRAPHS * 128];

// ============================ small kernels =================================

__global__ void convert_weight_all(const float* __restrict__ W0,
                                   const float* __restrict__ W1,
                                   const float* __restrict__ W2,
                                   const float* __restrict__ W3,
                                   const float* __restrict__ W4,
                                   const float* __restrict__ W5,
                                   const float* __restrict__ W6,
                                   __nv_bfloat16* __restrict__ Whi) {
    int w = blockIdx.y;
    const float* W = (w == 0) ? W0 : (w == 1) ? W1 : (w == 2) ? W2 :
                     (w == 3) ? W3 : (w == 4) ? W4 : (w == 5) ? W5 : W6;
    int n = blockIdx.x;   // 256
    int k = threadIdx.x;  // 256
    float v = W[k * HID + n];
    Whi[(size_t)w * HID * HID + n * HID + k] = __float2bfloat16(v);
}

__global__ void count_kernel(const int* __restrict__ batch,
                             float* __restrict__ counts) {
    int i = blockIdx.x * blockDim.x + threadIdx.x;
    if (i >= N_NODES) return;
    atomicAdd(&counts[batch[i]], 1.0f);
}

__global__ void scatter_add_7(const float* __restrict__ x,
                              const int* __restrict__ ei,
                              float* __restrict__ agg) {
    int e = blockIdx.x * blockDim.x + threadIdx.x;
    if (e >= N_EDGES) return;
    int s = ei[e];
    int d = ei[N_EDGES + e];
#pragma unroll
    for (int j = 0; j < 7; j++)
        atomicAdd(&agg[(size_t)d * 7 + j], x[(size_t)s * 7 + j]);
}

__global__ void scatter_add_256(const float* __restrict__ x,
                                const int* __restrict__ ei,
                                float* __restrict__ agg) {
    int gw   = (blockIdx.x * blockDim.x + threadIdx.x) >> 5;
    int lane = threadIdx.x & 31;
    pdl_trigger();
    if (gw >= N_EDGES) return;
    int s = ei[gw];
    int d = ei[N_EDGES + gw];
    pdl_wait();
    const float* xs = x + (size_t)s * HID;
    float* ad = agg + (size_t)d * HID;
#pragma unroll
    for (int j = 0; j < 8; j++)
        atomicAdd(ad + lane + 32 * j, xs[lane + 32 * j]);
}

// layer-1 first GEMM (K=7): 64 threads per node, 4 cols/thread
#define K7_BLOCKS 1184
__global__ void gemm_k7_relu_split(const float* __restrict__ A,
                                   const float* __restrict__ W,
                                   const float* __restrict__ bias,
                                   __nv_bfloat16* __restrict__ Chi,
                                   __nv_bfloat16* __restrict__ Clo) {
    const int grp = threadIdx.x >> 6;
    const int c4  = (threadIdx.x & 63) << 2;

    float w[7][4];
#pragma unroll
    for (int j = 0; j < 7; j++) {
        float4 wv = *reinterpret_cast<const float4*>(&W[j * HID + c4]);
        w[j][0] = wv.x; w[j][1] = wv.y; w[j][2] = wv.z; w[j][3] = wv.w;
    }
    float4 bv = *reinterpret_cast<const float4*>(&bias[c4]);
    float bi[4] = {bv.x, bv.y, bv.z, bv.w};

    for (int m = blockIdx.x * 4 + grp; m < N_NODES; m += K7_BLOCKS * 4) {
        const float* xr = A + (size_t)m * 7;
        float x0 = xr[0], x1 = xr[1], x2 = xr[2], x3 = xr[3];
        float x4 = xr[4], x5 = xr[5], x6 = xr[6];
        float acc[4];
#pragma unroll
        for (int i = 0; i < 4; i++) {
            float a = bi[i];
            a = fmaf(x0, w[0][i], a);
            a = fmaf(x1, w[1][i], a);
            a = fmaf(x2, w[2][i], a);
            a = fmaf(x3, w[3][i], a);
            a = fmaf(x4, w[4][i], a);
            a = fmaf(x5, w[5][i], a);
            a = fmaf(x6, w[6][i], a);
            acc[i] = fmaxf(a, 0.0f);
        }
        uint2 hp, lp;
        hp.x = pack_bf16x2(acc[0], acc[1]);
        hp.y = pack_bf16x2(acc[2], acc[3]);
        lp.x = pack_bf16x2(acc[0] - __bfloat162float(__float2bfloat16(acc[0])),
                           acc[1] - __bfloat162float(__float2bfloat16(acc[1])));
        lp.y = pack_bf16x2(acc[2] - __bfloat162float(__float2bfloat16(acc[2])),
                           acc[3] - __bfloat162float(__float2bfloat16(acc[3])));
        *reinterpret_cast<uint2*>(Chi + (size_t)m * HID + c4) = hp;
        *reinterpret_cast<uint2*>(Clo + (size_t)m * HID + c4) = lp;
    }
}

// ======= GEMM variant 1: bf16 A (2-term: exact-A x bf16-W), 3-stage =========
// D = (Ahi+Alo) @ Bhi^T  (exact activations, bf16 weights)
// mode 0: Cf (+Cc) fp32 out.  mode 1: Chi/Clo bf16 split out.
// mode 2: atomic mean-pool accumulate.

#define TILE_SW  8192
#define STAGE_SW (3 * TILE_SW)          // Ahi, Alo, Bhi
#define GEMM_SMEM (3 * STAGE_SW)        // 73728

__device__ __forceinline__ uint32_t swz(int row, uint32_t kcol) {
    return (uint32_t)(row * 64) + (((kcol ^ ((uint32_t)(row >> 1) & 3u)) << 4));
}

__global__ __launch_bounds__(256, 2)
void mma_gemm_split(int M,
                    const uint4* __restrict__ Ahi4, const uint4* __restrict__ Alo4,
                    const uint4* __restrict__ Bhi4,
                    const float* __restrict__ bias,
                    float* __restrict__ Cf, float* __restrict__ Cc,
                    __nv_bfloat16* __restrict__ Chi,
                    __nv_bfloat16* __restrict__ Clo,
                    const int* __restrict__ batch,
                    float* __restrict__ pooled,
                    int mode) {
    extern __shared__ char smem[];
    const uint32_t sb = smem_u32(smem);

    const int tid  = threadIdx.x;
    const int wid  = tid >> 5;
    const int lane = tid & 31;
    const int wm   = wid & 1;
    const int wn   = wid >> 1;
    const int block_col = blockIdx.x * 128;
    const int block_row = blockIdx.y * 128;

    const int a_lrow = lane & 15;
    const int a_lcol = (lane >> 4) << 3;
    const int b_lrow = (lane & 7) + ((lane >> 4) & 1) * 8;
    const int b_lcol = ((lane >> 3) & 1) << 3;
    const uint32_t a_k0 = (uint32_t)(a_lcol >> 3);
    const uint32_t b_k0 = (uint32_t)(b_lcol >> 3);

    uint32_t a_rowoff[4], b_rowoff[2];
    uint32_t a_s[4], b_s[2];
#pragma unroll
    for (int f = 0; f < 4; f++) {
        int r = wm * 64 + f * 16 + a_lrow;
        a_rowoff[f] = (uint32_t)(r * 64);
        a_s[f] = (uint32_t)(r >> 1) & 3u;
    }
#pragma unroll
    for (int p = 0; p < 2; p++) {
        int r = wn * 32 + p * 16 + b_lrow;
        b_rowoff[p] = (uint32_t)(r * 64);
        b_s[p] = (uint32_t)(r >> 1) & 3u;
    }

    float acc[4][4][4];
#pragma unroll
    for (int i = 0; i < 4; i++)
#pragma unroll
        for (int j = 0; j < 4; j++)
#pragma unroll
            for (int c = 0; c < 4; c++) acc[i][j][c] = 0.0f;

    const int ldrow = tid >> 2;
    const int ldc   = tid & 3;

    auto issueB = [&](int kc) {
        uint32_t sbase = sb + (uint32_t)(kc % 3) * STAGE_SW;
#pragma unroll
        for (int h = 0; h < 2; h++) {
            int row = ldrow + h * 64;
            size_t gB = (size_t)(block_col + row) * 32 + kc * 4 + ldc;
            cp_async16(sbase + 2 * TILE_SW + swz(row, (uint32_t)ldc), Bhi4 + gB);
        }
    };
    auto issueA = [&](int kc) {
        uint32_t sbase = sb + (uint32_t)(kc % 3) * STAGE_SW;
#pragma unroll
        for (int h = 0; h < 2; h++) {
            int row = ldrow + h * 64;
            int rg = block_row + row;
            if (rg >= M) rg = M - 1;
            size_t gA = (size_t)rg * 32 + kc * 4 + ldc;
            uint32_t so = swz(row, (uint32_t)ldc);
            cp_async16(sbase + 0 * TILE_SW + so, Ahi4 + gA);
            cp_async16(sbase + 1 * TILE_SW + so, Alo4 + gA);
        }
    };

    issueB(0);
    issueB(1);
    pdl_wait();
    issueA(0); CP_COMMIT();
    issueA(1); CP_COMMIT();

    for (int kc = 0; kc < 8; kc++) {
        CP_WAIT(1);
        __syncthreads();
        if (kc < 6) { issueA(kc + 2); issueB(kc + 2); CP_COMMIT(); }

        uint32_t base = sb + (uint32_t)(kc % 3) * STAGE_SW;
        uint32_t uAhi = base + 0 * TILE_SW;
        uint32_t uAlo = base + 1 * TILE_SW;
        uint32_t uBhi = base + 2 * TILE_SW;

        uint32_t ah[4][4], al[4][4], bh[2][4];
#pragma unroll
        for (int ks16 = 0; ks16 < 2; ks16++) {
            const uint32_t kb = (uint32_t)(ks16 * 2);
#pragma unroll
            for (int f = 0; f < 4; f++) {
                uint32_t off = a_rowoff[f] + (((a_k0 + kb) ^ a_s[f]) << 4);
                ldsm_x4(uAhi + off, ah[f]);
                ldsm_x4(uAlo + off, al[f]);
            }
#pragma unroll
            for (int p = 0; p < 2; p++) {
                uint32_t off = b_rowoff[p] + (((b_k0 + kb) ^ b_s[p]) << 4);
                ldsm_x4(uBhi + off, bh[p]);
            }
#pragma unroll
            for (int mf = 0; mf < 4; mf++)
#pragma unroll
                for (int nf = 0; nf < 4; nf++) {
                    int p = nf >> 1, q = (nf & 1) * 2;
                    mma16816(acc[mf][nf], ah[mf], bh[p][q], bh[p][q + 1]);
                    mma16816(acc[mf][nf], al[mf], bh[p][q], bh[p][q + 1]);
                }
        }
    }

    pdl_trigger();

    // ---- epilogue ----
#pragma unroll
    for (int mf = 0; mf < 4; mf++) {
        int r0 = block_row + wm * 64 + mf * 16 + (lane >> 2);
        int r1 = r0 + 8;
#pragma unroll
        for (int nf = 0; nf < 4; nf++) {
            int col = block_col + wn * 32 + nf * 8 + (lane & 3) * 2;
            float b0 = bias[col], b1 = bias[col + 1];
            float v00 = fmaxf(acc[mf][nf][0] + b0, 0.f);
            float v01 = fmaxf(acc[mf][nf][1] + b1, 0.f);
            float v10 = fmaxf(acc[mf][nf][2] + b0, 0.f);
            float v11 = fmaxf(acc[mf][nf][3] + b1, 0.f);
            if (mode == 0) {
                if (r0 < M) {
                    *reinterpret_cast<float2*>(&Cf[(size_t)r0 * HID + col]) =
                        make_float2(v00, v01);
                    *reinterpret_cast<float2*>(&Cc[(size_t)r0 * HID + col]) =
                        make_float2(v00, v01);
                }
                if (r1 < M) {
                    *reinterpret_cast<float2*>(&Cf[(size_t)r1 * HID + col]) =
                        make_float2(v10, v11);
                    *reinterpret_cast<float2*>(&Cc[(size_t)r1 * HID + col]) =
                        make_float2(v10, v11);
                }
            } else if (mode == 1) {
                uint32_t hp0 = pack_bf16x2(v00, v01);
                uint32_t hp1 = pack_bf16x2(v10, v11);
                float w00 = v00 - __bfloat162float(__float2bfloat16(v00));
                float w01 = v01 - __bfloat162float(__float2bfloat16(v01));
                float w10 = v10 - __bfloat162float(__float2bfloat16(v10));
                float w11 = v11 - __bfloat162float(__float2bfloat16(v11));
                uint32_t lp0 = pack_bf16x2(w00, w01);
                uint32_t lp1 = pack_bf16x2(w10, w11);
                if (r0 < M) {
                    *reinterpret_cast<uint32_t*>(Chi + (size_t)r0 * HID + col) = hp0;
                    *reinterpret_cast<uint32_t*>(Clo + (size_t)r0 * HID + col) = lp0;
                }
                if (r1 < M) {
                    *reinterpret_cast<uint32_t*>(Chi + (size_t)r1 * HID + col) = hp1;
                    *reinterpret_cast<uint32_t*>(Clo + (size_t)r1 * HID + col) = lp1;
                }
            } else {
                if (r0 < M) {
                    float* pd = pooled + (size_t)batch[r0] * HID + col;
                    atomicAdd(pd + 0, v00);
                    atomicAdd(pd + 1, v01);
                }
                if (r1 < M) {
                    float* pd = pooled + (size_t)batch[r1] * HID + col;
                    atomicAdd(pd + 0, v10);
                    atomicAdd(pd + 1, v11);
                }
            }
        }
    }
}

// ======= GEMM variant 2: fp32 A, in-kernel split, 2-term, 3-stage ===========

#define F_A32_STG 16384
#define F_B_OFF   (3 * F_A32_STG)          // 49152
#define F_B_STG   TILE_SW                   // 8192 (Bhi only)
#define F_AHI     (F_B_OFF + 3 * F_B_STG)  // 73728
#define F_ALO     (F_AHI + TILE_SW)        // 81920
#define F_SMEM    (F_ALO + TILE_SW)        // 90112

__global__ __launch_bounds__(256, 2)
void mma_gemm_split_f32a(int M,
                         const float* __restrict__ Af,
                         const uint4* __restrict__ Bhi4,
                         const float* __restrict__ bias,
                         __nv_bfloat16* __restrict__ Chi,
                         __nv_bfloat16* __restrict__ Clo) {
    extern __shared__ char smem[];
    const uint32_t sb = smem_u32(smem);

    const int tid  = threadIdx.x;
    const int wid  = tid >> 5;
    const int lane = tid & 31;
    const int wm   = wid & 1;
    const int wn   = wid >> 1;
    const int block_col = blockIdx.x * 128;
    const int block_row = blockIdx.y * 128;

    const int a_lrow = lane & 15;
    const int a_lcol = (lane >> 4) << 3;
    const int b_lrow = (lane & 7) + ((lane >> 4) & 1) * 8;
    const int b_lcol = ((lane >> 3) & 1) << 3;
    const uint32_t a_k0 = (uint32_t)(a_lcol >> 3);
    const uint32_t b_k0 = (uint32_t)(b_lcol >> 3);

    uint32_t a_rowoff[4], b_rowoff[2];
    uint32_t a_s[4], b_s[2];
#pragma unroll
    for (int f = 0; f < 4; f++) {
        int r = wm * 64 + f * 16 + a_lrow;
        a_rowoff[f] = (uint32_t)(r * 64);
        a_s[f] = (uint32_t)(r >> 1) & 3u;
    }
#pragma unroll
    for (int p = 0; p < 2; p++) {
        int r = wn * 32 + p * 16 + b_lrow;
        b_rowoff[p] = (uint32_t)(r * 64);
        b_s[p] = (uint32_t)(r >> 1) & 3u;
    }

    float acc[4][4][4];
#pragma unroll
    for (int i = 0; i < 4; i++)
#pragma unroll
        for (int j = 0; j < 4; j++)
#pragma unroll
            for (int c = 0; c < 4; c++) acc[i][j][c] = 0.0f;

    const int ldrow = tid >> 2;
    const int ldc   = tid & 3;
    const int crow  = tid >> 1;
    const int chalf = tid & 1;

    auto issueB = [&](int kc) {
        uint32_t bbase = sb + F_B_OFF + (uint32_t)(kc % 3) * F_B_STG;
#pragma unroll
        for (int h = 0; h < 2; h++) {
            int row = ldrow + h * 64;
            size_t gB = (size_t)(block_col + row) * 32 + kc * 4 + ldc;
            cp_async16(bbase + swz(row, (uint32_t)ldc), Bhi4 + gB);
        }
    };
    auto issueA = [&](int kc) {
        int s = kc % 3;
#pragma unroll
        for (int i = 0; i < 4; i++) {
            int idx = tid + i * 256;
            int row = idx >> 3, c = idx & 7;
            int rg = block_row + row;
            if (rg >= M) rg = M - 1;
            const float* g = Af + (size_t)rg * 256 + kc * 32 + c * 4;
            uint32_t so = (uint32_t)(row * 128) +
                          (((uint32_t)(c ^ (row & 7))) << 4);
            cp_async16(sb + (uint32_t)(s * F_A32_STG) + so, g);
        }
    };

    issueB(0);
    issueB(1);
    pdl_wait();
    issueA(0); CP_COMMIT();
    issueA(1); CP_COMMIT();

    for (int kc = 0; kc < 8; kc++) {
        CP_WAIT(1);
        __syncthreads();
        if (kc < 6) { issueA(kc + 2); issueB(kc + 2); CP_COMMIT(); }

        {
            const char* afb = smem + (kc % 3) * F_A32_STG + crow * 128;
            uint32_t rs = (uint32_t)(crow & 7);
            float4 v0 = *reinterpret_cast<const float4*>(
                afb + (((uint32_t)(chalf * 4 + 0) ^ rs) << 4));
            float4 v1 = *reinterpret_cast<const float4*>(
                afb + (((uint32_t)(chalf * 4 + 1) ^ rs) << 4));
            float4 v2 = *reinterpret_cast<const float4*>(
                afb + (((uint32_t)(chalf * 4 + 2) ^ rs) << 4));
            float4 v3 = *reinterpret_cast<const float4*>(
                afb + (((uint32_t)(chalf * 4 + 3) ^ rs) << 4));
            uint4 H0, H1, L0, L1;
            H0.x = pack_bf16x2(v0.x, v0.y); H0.y = pack_bf16x2(v0.z, v0.w);
            H0.z = pack_bf16x2(v1.x, v1.y); H0.w = pack_bf16x2(v1.z, v1.w);
            H1.x = pack_bf16x2(v2.x, v2.y); H1.y = pack_bf16x2(v2.z, v2.w);
            H1.z = pack_bf16x2(v3.x, v3.y); H1.w = pack_bf16x2(v3.z, v3.w);
            L0.x = pack_bf16x2(v0.x - __bfloat162float(__float2bfloat16(v0.x)),
                               v0.y - __bfloat162float(__float2bfloat16(v0.y)));
            L0.y = pack_bf16x2(v0.z - __bfloat162float(__float2bfloat16(v0.z)),
                               v0.w - __bfloat162float(__float2bfloat16(v0.w)));
            L0.z = pack_bf16x2(v1.x - __bfloat162float(__float2bfloat16(v1.x)),
                               v1.y - __bfloat162float(__float2bfloat16(v1.y)));
            L0.w = pack_bf16x2(v1.z - __bfloat162float(__float2bfloat16(v1.z)),
                               v1.w - __bfloat162float(__float2bfloat16(v1.w)));
            L1.x = pack_bf16x2(v2.x - __bfloat162float(__float2bfloat16(v2.x)),
                               v2.y - __bfloat162float(__float2bfloat16(v2.y)));
            L1.y = pack_bf16x2(v2.z - __bfloat162float(__float2bfloat16(v2.z)),
                               v2.w - __bfloat162float(__float2bfloat16(v2.w)));
            L1.z = pack_bf16x2(v3.x - __bfloat162float(__float2bfloat16(v3.x)),
                               v3.y - __bfloat162float(__float2bfloat16(v3.y)));
            L1.w = pack_bf16x2(v3.z - __bfloat162float(__float2bfloat16(v3.z)),
                               v3.w - __bfloat162float(__float2bfloat16(v3.w)));
            uint32_t cs = (uint32_t)(crow >> 1) & 3u;
            uint32_t g0 = ((uint32_t)(chalf * 2 + 0) ^ cs) << 4;
            uint32_t g1 = ((uint32_t)(chalf * 2 + 1) ^ cs) << 4;
            char* ah = smem + F_AHI + crow * 64;
            char* al = smem + F_ALO + crow * 64;
            *reinterpret_cast<uint4*>(ah + g0) = H0;
            *reinterpret_cast<uint4*>(ah + g1) = H1;
            *reinterpret_cast<uint4*>(al + g0) = L0;
            *reinterpret_cast<uint4*>(al + g1) = L1;
        }
        __syncthreads();

        uint32_t uAhi = sb + F_AHI;
        uint32_t uAlo = sb + F_ALO;
        uint32_t uBhi = sb + F_B_OFF + (uint32_t)(kc % 3) * F_B_STG;

        uint32_t ah[4][4], al[4][4], bh[2][4];
#pragma unroll
        for (int ks16 = 0; ks16 < 2; ks16++) {
            const uint32_t kb = (uint32_t)(ks16 * 2);
#pragma unroll
            for (int f = 0; f < 4; f++) {
                uint32_t off = a_rowoff[f] + (((a_k0 + kb) ^ a_s[f]) << 4);
                ldsm_x4(uAhi + off, ah[f]);
                ldsm_x4(uAlo + off, al[f]);
            }
#pragma unroll
            for (int p = 0; p < 2; p++) {
                uint32_t off = b_rowoff[p] + (((b_k0 + kb) ^ b_s[p]) << 4);
                ldsm_x4(uBhi + off, bh[p]);
            }
#pragma unroll
            for (int mf = 0; mf < 4; mf++)
#pragma unroll
                for (int nf = 0; nf < 4; nf++) {
                    int p = nf >> 1, q = (nf & 1) * 2;
                    mma16816(acc[mf][nf], ah[mf], bh[p][q], bh[p][q + 1]);
                    mma16816(acc[mf][nf], al[mf], bh[p][q], bh[p][q + 1]);
                }
        }
    }

    pdl_trigger();

#pragma unroll
    for (int mf = 0; mf < 4; mf++) {
        int r0 = block_row + wm * 64 + mf * 16 + (lane >> 2);
        int r1 = r0 + 8;
#pragma unroll
        for (int nf = 0; nf < 4; nf++) {
            int col = block_col + wn * 32 + nf * 8 + (lane & 3) * 2;
            float b0 = bias[col], b1 = bias[col + 1];
            float v00 = fmaxf(acc[mf][nf][0] + b0, 0.f);
            float v01 = fmaxf(acc[mf][nf][1] + b1, 0.f);
            float v10 = fmaxf(acc[mf][nf][2] + b0, 0.f);
            float v11 = fmaxf(acc[mf][nf][3] + b1, 0.f);
            uint32_t hp0 = pack_bf16x2(v00, v01);
            uint32_t hp1 = pack_bf16x2(v10, v11);
            float w00 = v00 - __bfloat162float(__float2bfloat16(v00));
            float w01 = v01 - __bfloat162float(__float2bfloat16(v01));
            float w10 = v10 - __bfloat162float(__float2bfloat16(v10));
            float w11 = v11 - __bfloat162float(__float2bfloat16(v11));
            uint32_t lp0 = pack_bf16x2(w00, w01);
            uint32_t lp1 = pack_bf16x2(w10, w11);
            if (r0 < M) {
                *reinterpret_cast<uint32_t*>(Chi + (size_t)r0 * HID + col) = hp0;
                *reinterpret_cast<uint32_t*>(Clo + (size_t)r0 * HID + col) = lp0;
            }
            if (r1 < M) {
                *reinterpret_cast<uint32_t*>(Chi + (size_t)r1 * HID + col) = hp1;
                *reinterpret_cast<uint32_t*>(Clo + (size_t)r1 * HID + col) = lp1;
            }
        }
    }
}

// ====== fp32 tiled SGEMM (head GEMM) with fused mean-divide =================

__global__ __launch_bounds__(256)
void sgemm_bias_relu(int M, const float* __restrict__ A,
                     const float* __restrict__ B,
                     const float* __restrict__ bias,
                     float* __restrict__ C,
                     int N, int K, int doRelu,
                     const float* __restrict__ rowdiv) {
    __shared__ float As[8][128];
    __shared__ float Bs[8][128];

    const int tid       = threadIdx.x;
    const int block_row = blockIdx.y * 128;
    const int block_col = blockIdx.x * 128;

    const int aRow = tid >> 1;
    const int aCol = (tid & 1) << 2;
    const int bRow = tid >> 5;
    const int bCol = (tid & 31) << 2;
    const int trow = (tid >> 4) << 3;
    const int tcol = (tid & 15) << 3;

    float rdiv = 1.0f;
    if (rowdiv && block_row + aRow < M)
        rdiv = 1.0f / fmaxf(rowdiv[block_row + aRow], 1.0f);

    float acc[8][8];
#pragma unroll
    for (int i = 0; i < 8; i++)
#pragma unroll
        for (int j = 0; j < 8; j++) acc[i][j] = 0.0f;

    for (int kt = 0; kt < K; kt += 8) {
        float4 av = make_float4(0.f, 0.f, 0.f, 0.f);
        if (block_row + aRow < M)
            av = *reinterpret_cast<const float4*>(&A[(size_t)(block_row + aRow) * K + kt + aCol]);
        As[aCol + 0][aRow] = av.x * rdiv;
        As[aCol + 1][aRow] = av.y * rdiv;
        As[aCol + 2][aRow] = av.z * rdiv;
        As[aCol + 3][aRow] = av.w * rdiv;

        float4 bv = *reinterpret_cast<const float4*>(&B[(size_t)(kt + bRow) * N + block_col + bCol]);
        *reinterpret_cast<float4*>(&Bs[bRow][bCol]) = bv;
        __syncthreads();

#pragma unroll
        for (int k = 0; k < 8; k++) {
            float ra[8], rb[8];
#pragma unroll
            for (int i = 0; i < 8; i++) ra[i] = As[k][trow + i];
#pragma unroll
            for (int j = 0; j < 8; j++) rb[j] = Bs[k][tcol + j];
#pragma unroll
            for (int i = 0; i < 8; i++)
#pragma unroll
                for (int j = 0; j < 8; j++)
                    acc[i][j] = fmaf(ra[i], rb[j], acc[i][j]);
        }
        __syncthreads();
    }

#pragma unroll
    for (int i = 0; i < 8; i++) {
        int r = block_row + trow + i;
        if (r < M) {
#pragma unroll
            for (int j = 0; j < 8; j += 4) {
                float4 v;
                v.x = acc[i][j + 0] + bias[block_col + tcol + j + 0];
                v.y = acc[i][j + 1] + bias[block_col + tcol + j + 1];
                v.z = acc[i][j + 2] + bias[block_col + tcol + j + 2];
                v.w = acc[i][j + 3] + bias[block_col + tcol + j + 3];
                if (doRelu) {
                    v.x = fmaxf(v.x, 0.f); v.y = fmaxf(v.y, 0.f);
                    v.z = fmaxf(v.z, 0.f); v.w = fmaxf(v.w, 0.f);
                }
                *reinterpret_cast<float4*>(&C[(size_t)r * N + block_col + tcol + j]) = v;
            }
        }
    }
}

// ============================ head final ====================================

__global__ void head_final(const float* __restrict__ hid,
                           const float* __restrict__ W,
                           const float* __restrict__ b,
                           float* __restrict__ out) {
    int m = blockIdx.x * blockDim.x + threadIdx.x;
    if (m >= N_GRAPHS) return;
    float a0 = b[0], a1 = b[1], a2 = b[2];
    const float* hs = hid + (size_t)m * 128;
#pragma unroll 8
    for (int k = 0; k < 128; k++) {
        float h = hs[k];
        a0 = fmaf(h, W[k * 3 + 0], a0);
        a1 = fmaf(h, W[k * 3 + 1], a1);
        a2 = fmaf(h, W[k * 3 + 2], a2);
    }
    out[m * 3 + 0] = a0;
    out[m * 3 + 1] = a1;
    out[m * 3 + 2] = a2;
}

// ============================ launch ========================================

template <typename F, typename... Args>
static void launch_pdl(F* kernel, dim3 grid, dim3 block, size_t smem,
                       Args... args) {
    cudaLaunchConfig_t cfg = {};
    cfg.gridDim = grid;
    cfg.blockDim = block;
    cfg.dynamicSmemBytes = smem;
    cfg.stream = 0;
    cudaLaunchAttribute attr[1];
    attr[0].id = cudaLaunchAttributeProgrammaticStreamSerialization;
    attr[0].val.programmaticStreamSerializationAllowed = 1;
    cfg.attrs = attr;
    cfg.numAttrs = 1;
    cudaLaunchKernelEx(&cfg, kernel, args...);
}

extern "C" void kernel_launch(void* const* d_in, const int* in_sizes, int n_in,
                              void* d_out, int out_size) {
    const float* x     = (const float*)d_in[0];
    const int*   ei    = (const int*)d_in[1];
    const int*   batch = (const int*)d_in[2];

    const float* Wa[4], *ba[4], *Wb[4], *bb[4];
    for (int l = 0; l < 4; l++) {
        Wa[l] = (const float*)d_in[3 + 4 * l + 0];
        ba[l] = (const float*)d_in[3 + 4 * l + 1];
        Wb[l] = (const float*)d_in[3 + 4 * l + 2];
        bb[l] = (const float*)d_in[3 + 4 * l + 3];
    }
    const float* Wh1 = (const float*)d_in[19];
    const float* bh1 = (const float*)d_in[20];
    const float* Wh2 = (const float*)d_in[21];
    const float* bh2 = (const float*)d_in[22];
    float* out = (float*)d_out;

    __nv_bfloat16 *A2hi, *A2lo, *Whi;
    float *bufB, *bufC, *agg7, *pooled, *counts, *hid;
    cudaGetSymbolAddress((void**)&A2hi,   g_A2hi);
    cudaGetSymbolAddress((void**)&A2lo,   g_A2lo);
    cudaGetSymbolAddress((void**)&Whi,    g_Whi);
    cudaGetSymbolAddress((void**)&bufB,   g_bufB);
    cudaGetSymbolAddress((void**)&bufC,   g_bufC);
    cudaGetSymbolAddress((void**)&agg7,   g_agg7);
    cudaGetSymbolAddress((void**)&pooled, g_pooled);
    cudaGetSymbolAddress((void**)&counts, g_counts);
    cudaGetSymbolAddress((void**)&hid,    g_hid);

    cudaFuncSetAttribute(mma_gemm_split,
                         cudaFuncAttributeMaxDynamicSharedMemorySize, GEMM_SMEM);
    cudaFuncSetAttribute(mma_gemm_split_f32a,
                         cudaFuncAttributeMaxDynamicSharedMemorySize, F_SMEM);

    // ---- prologue: weights, counts, pooled init ----
    dim3 cw_grid(HID, 7);
    convert_weight_all<<<cw_grid, HID>>>(Wb[0], Wa[1], Wb[1], Wa[2], Wb[2],
                                         Wa[3], Wb[3], Whi);
    cudaMemsetAsync(pooled, 0, (size_t)N_GRAPHS * HID * sizeof(float));
    cudaMemsetAsync(counts, 0, (size_t)N_GRAPHS * sizeof(float));
    count_kernel<<<(N_NODES + 255) / 256, 256>>>(batch, counts);

    dim3 mma_grid(2, (N_NODES + 127) / 128);
    dim3 sc_grid((unsigned)(((size_t)N_EDGES * 32 + 255) / 256));

    // ---- layer 1 ----
    cudaMemcpyAsync(agg7, x, (size_t)N_NODES * 7 * sizeof(float),
                    cudaMemcpyDeviceToDevice);
    scatter_add_7<<<(N_EDGES + 255) / 256, 256>>>(x, ei, agg7);
    gemm_k7_relu_split<<<K7_BLOCKS, 256>>>(agg7, Wa[0], ba[0], A2hi, A2lo);
    launch_pdl(mma_gemm_split, mma_grid, dim3(256), (size_t)GEMM_SMEM,
               N_NODES, (const uint4*)A2hi, (const uint4*)A2lo,
               (const uint4*)Whi,
               bb[0], bufB, bufC, (__nv_bfloat16*)nullptr,
               (__nv_bfloat16*)nullptr, (const int*)nullptr,
               (float*)nullptr, 0);

    // ---- layers 2..4 ----
    for (int l = 1; l < 4; l++) {
        launch_pdl(scatter_add_256, sc_grid, dim3(256), (size_t)0,
                   (const float*)bufB, ei, bufC);
        launch_pdl(mma_gemm_split_f32a, mma_grid, dim3(256), (size_t)F_SMEM,
                   N_NODES, (const float*)bufC,
                   (const uint4*)(Whi + (size_t)(2 * l - 1) * HID * HID),
                   ba[l], A2hi, A2lo);
        if (l < 3) {
            launch_pdl(mma_gemm_split, mma_grid, dim3(256), (size_t)GEMM_SMEM,
                       N_NODES, (const uint4*)A2hi, (const uint4*)A2lo,
                       (const uint4*)(Whi + (size_t)(2 * l) * HID * HID),
                       bb[l], bufB, bufC, (__nv_bfloat16*)nullptr,
                       (__nv_bfloat16*)nullptr, (const int*)nullptr,
                       (float*)nullptr, 0);
        } else {
            launch_pdl(mma_gemm_split, mma_grid, dim3(256), (size_t)GEMM_SMEM,
                       N_NODES, (const uint4*)A2hi, (const uint4*)A2lo,
                       (const uint4*)(Whi + (size_t)(2 * l) * HID * HID),
                       bb[l], (float*)nullptr, (float*)nullptr,
                       (__nv_bfloat16*)nullptr, (__nv_bfloat16*)nullptr,
                       batch, pooled, 2);
        }
    }

    // ---- head (mean-divide fused into A load) ----
    dim3 head_grid(1, (N_GRAPHS + 127) / 128);
    sgemm_bias_relu<<<head_grid, 256>>>(N_GRAPHS, pooled, Wh1, bh1, hid,
                                        128, 256, 1, counts);
    head_final<<<(N_GRAPHS + 255) / 256, 256>>>(hid, Wh2, bh2, out);
}

// round 17
// speedup vs baseline: 1.1691x; 1.0043x over previous
#include <cuda_runtime.h>
#include <cuda_bf16.h>
#include <cstdint>

#define N_NODES  150000
#define N_EDGES  300000
#define N_GRAPHS 6000
#define HID      256

// ============================ helpers =======================================

__device__ __forceinline__ uint32_t smem_u32(const void* p) {
    uint32_t addr;
    asm("{ .reg .u64 tmp; cvta.to.shared.u64 tmp, %1; cvt.u32.u64 %0, tmp; }"
        : "=r"(addr) : "l"(p));
    return addr;
}

__device__ __forceinline__ void ldsm_x4(uint32_t addr, uint32_t* r) {
    asm volatile("ldmatrix.sync.aligned.m8n8.x4.shared.b16 {%0,%1,%2,%3}, [%4];"
                 : "=r"(r[0]), "=r"(r[1]), "=r"(r[2]), "=r"(r[3]) : "r"(addr));
}

__device__ __forceinline__ void mma16816(float* d, const uint32_t* a,
                                         uint32_t b0, uint32_t b1) {
    asm volatile(
        "mma.sync.aligned.m16n8k16.row.col.f32.bf16.bf16.f32 "
        "{%0,%1,%2,%3}, {%4,%5,%6,%7}, {%8,%9}, {%0,%1,%2,%3};"
        : "+f"(d[0]), "+f"(d[1]), "+f"(d[2]), "+f"(d[3])
        : "r"(a[0]), "r"(a[1]), "r"(a[2]), "r"(a[3]), "r"(b0), "r"(b1));
}

__device__ __forceinline__ void cp_async16(uint32_t smem_addr, const void* g) {
    asm volatile("cp.async.cg.shared.global [%0], [%1], 16;"
                 :: "r"(smem_addr), "l"(g));
}
#define CP_COMMIT() asm volatile("cp.async.commit_group;" ::: "memory")
#define CP_WAIT(n)  asm volatile("cp.async.wait_group %0;" :: "n"(n) : "memory")

__device__ __forceinline__ uint32_t pack_bf16x2(float a, float b) {
    __nv_bfloat16 ha = __float2bfloat16(a);
    __nv_bfloat16 hb = __float2bfloat16(b);
    return ((uint32_t)__bfloat16_as_ushort(hb) << 16) | __bfloat16_as_ushort(ha);
}

__device__ __forceinline__ void pdl_trigger() {
    asm volatile("griddepcontrol.launch_dependents;");
}
__device__ __forceinline__ void pdl_wait() {
    asm volatile("griddepcontrol.wait;" ::: "memory");
}

// ============================ scratch buffers ===============================

__device__ __nv_bfloat16 g_A2hi[(size_t)N_NODES * HID];
__device__ __nv_bfloat16 g_A2lo[(size_t)N_NODES * HID];
__device__ float g_bufB[(size_t)N_NODES * HID];   // layer output h (gather src)
__device__ float g_bufC[(size_t)N_NODES * HID];   // scatter accumulator (init h)
__device__ float g_agg7[N_NODES * 7];
__device__ __nv_bfloat16 g_Whi[7 * HID * HID];    // weights, [N][K] bf16 hi
__device__ float g_pooled[N_GRAPHS * HID];
__device__ float g_counts[N_GRAPHS];
__device__ float g_hid[N_GRAPHS * 128];

// ============================ small kernels =================================

__global__ void convert_weight_all(const float* __restrict__ W0,
                                   const float* __restrict__ W1,
                                   const float* __restrict__ W2,
                                   const float* __restrict__ W3,
                                   const float* __restrict__ W4,
                                   const float* __restrict__ W5,
                                   const float* __restrict__ W6,
                                   __nv_bfloat16* __restrict__ Whi) {
    int w = blockIdx.y;
    const float* W = (w == 0) ? W0 : (w == 1) ? W1 : (w == 2) ? W2 :
                     (w == 3) ? W3 : (w == 4) ? W4 : (w == 5) ? W5 : W6;
    int n = blockIdx.x;   // 256
    int k = threadIdx.x;  // 256
    float v = W[k * HID + n];
    Whi[(size_t)w * HID * HID + n * HID + k] = __float2bfloat16(v);
}

__global__ void count_kernel(const int* __restrict__ batch,
                             float* __restrict__ counts) {
    int i = blockIdx.x * blockDim.x + threadIdx.x;
    if (i >= N_NODES) return;
    atomicAdd(&counts[batch[i]], 1.0f);
}

__global__ void scatter_add_7(const float* __restrict__ x,
                              const int* __restrict__ ei,
                              float* __restrict__ agg) {
    int e = blockIdx.x * blockDim.x + threadIdx.x;
    if (e >= N_EDGES) return;
    int s = ei[e];
    int d = ei[N_EDGES + e];
#pragma unroll
    for (int j = 0; j < 7; j++)
        atomicAdd(&agg[(size_t)d * 7 + j], x[(size_t)s * 7 + j]);
}

__global__ void scatter_add_256(const float* __restrict__ x,
                                const int* __restrict__ ei,
                                float* __restrict__ agg) {
    int gw   = (blockIdx.x * blockDim.x + threadIdx.x) >> 5;
    int lane = threadIdx.x & 31;
    pdl_trigger();
    if (gw >= N_EDGES) return;
    int s = ei[gw];
    int d = ei[N_EDGES + gw];
    pdl_wait();
    const float* xs = x + (size_t)s * HID;
    float* ad = agg + (size_t)d * HID;
#pragma unroll
    for (int j = 0; j < 8; j++)
        atomicAdd(ad + lane + 32 * j, xs[lane + 32 * j]);
}

// layer-1 first GEMM (K=7): 64 threads per node, 4 cols/thread
#define K7_BLOCKS 1184
__global__ void gemm_k7_relu_split(const float* __restrict__ A,
                                   const float* __restrict__ W,
                                   const float* __restrict__ bias,
                                   __nv_bfloat16* __restrict__ Chi,
                                   __nv_bfloat16* __restrict__ Clo) {
    const int grp = threadIdx.x >> 6;
    const int c4  = (threadIdx.x & 63) << 2;

    float w[7][4];
#pragma unroll
    for (int j = 0; j < 7; j++) {
        float4 wv = *reinterpret_cast<const float4*>(&W[j * HID + c4]);
        w[j][0] = wv.x; w[j][1] = wv.y; w[j][2] = wv.z; w[j][3] = wv.w;
    }
    float4 bv = *reinterpret_cast<const float4*>(&bias[c4]);
    float bi[4] = {bv.x, bv.y, bv.z, bv.w};

    for (int m = blockIdx.x * 4 + grp; m < N_NODES; m += K7_BLOCKS * 4) {
        const float* xr = A + (size_t)m * 7;
        float x0 = xr[0], x1 = xr[1], x2 = xr[2], x3 = xr[3];
        float x4 = xr[4], x5 = xr[5], x6 = xr[6];
        float acc[4];
#pragma unroll
        for (int i = 0; i < 4; i++) {
            float a = bi[i];
            a = fmaf(x0, w[0][i], a);
            a = fmaf(x1, w[1][i], a);
            a = fmaf(x2, w[2][i], a);
            a = fmaf(x3, w[3][i], a);
            a = fmaf(x4, w[4][i], a);
            a = fmaf(x5, w[5][i], a);
            a = fmaf(x6, w[6][i], a);
            acc[i] = fmaxf(a, 0.0f);
        }
        uint2 hp, lp;
        hp.x = pack_bf16x2(acc[0], acc[1]);
        hp.y = pack_bf16x2(acc[2], acc[3]);
        lp.x = pack_bf16x2(acc[0] - __bfloat162float(__float2bfloat16(acc[0])),
                           acc[1] - __bfloat162float(__float2bfloat16(acc[1])));
        lp.y = pack_bf16x2(acc[2] - __bfloat162float(__float2bfloat16(acc[2])),
                           acc[3] - __bfloat162float(__float2bfloat16(acc[3])));
        *reinterpret_cast<uint2*>(Chi + (size_t)m * HID + c4) = hp;
        *reinterpret_cast<uint2*>(Clo + (size_t)m * HID + c4) = lp;
    }
}

// ======= GEMM variant 1: bf16 A (2-term: exact-A x bf16-W), 3-stage =========
// D = (Ahi+Alo) @ Bhi^T  (exact activations, bf16 weights)
// mode 0: Cf (+Cc) fp32 out.  mode 1: Chi/Clo bf16 split out.
// mode 2: atomic mean-pool accumulate.

#define TILE_SW  8192
#define STAGE_SW (3 * TILE_SW)          // Ahi, Alo, Bhi
#define GEMM_SMEM (3 * STAGE_SW)        // 73728

__device__ __forceinline__ uint32_t swz(int row, uint32_t kcol) {
    return (uint32_t)(row * 64) + (((kcol ^ ((uint32_t)(row >> 1) & 3u)) << 4));
}

__global__ __launch_bounds__(256, 2)
void mma_gemm_split(int M,
                    const uint4* __restrict__ Ahi4, const uint4* __restrict__ Alo4,
                    const uint4* __restrict__ Bhi4,
                    const float* __restrict__ bias,
                    float* __restrict__ Cf, float* __restrict__ Cc,
                    __nv_bfloat16* __restrict__ Chi,
                    __nv_bfloat16* __restrict__ Clo,
                    const int* __restrict__ batch,
                    float* __restrict__ pooled,
                    int mode) {
    extern __shared__ char smem[];
    const uint32_t sb = smem_u32(smem);

    const int tid  = threadIdx.x;
    const int wid  = tid >> 5;
    const int lane = tid & 31;
    const int wm   = wid & 1;
    const int wn   = wid >> 1;
    const int block_col = blockIdx.x * 128;
    const int block_row = blockIdx.y * 128;

    const int a_lrow = lane & 15;
    const int a_lcol = (lane >> 4) << 3;
    const int b_lrow = (lane & 7) + ((lane >> 4) & 1) * 8;
    const int b_lcol = ((lane >> 3) & 1) << 3;
    const uint32_t a_k0 = (uint32_t)(a_lcol >> 3);
    const uint32_t b_k0 = (uint32_t)(b_lcol >> 3);

    uint32_t a_rowoff[4], b_rowoff[2];
    uint32_t a_s[4], b_s[2];
#pragma unroll
    for (int f = 0; f < 4; f++) {
        int r = wm * 64 + f * 16 + a_lrow;
        a_rowoff[f] = (uint32_t)(r * 64);
        a_s[f] = (uint32_t)(r >> 1) & 3u;
    }
#pragma unroll
    for (int p = 0; p < 2; p++) {
        int r = wn * 32 + p * 16 + b_lrow;
        b_rowoff[p] = (uint32_t)(r * 64);
        b_s[p] = (uint32_t)(r >> 1) & 3u;
    }

    float acc[4][4][4];
#pragma unroll
    for (int i = 0; i < 4; i++)
#pragma unroll
        for (int j = 0; j < 4; j++)
#pragma unroll
            for (int c = 0; c < 4; c++) acc[i][j][c] = 0.0f;

    const int ldrow = tid >> 2;
    const int ldc   = tid & 3;

    auto issueB = [&](int kc) {
        uint32_t sbase = sb + (uint32_t)(kc % 3) * STAGE_SW;
#pragma unroll
        for (int h = 0; h < 2; h++) {
            int row = ldrow + h * 64;
            size_t gB = (size_t)(block_col + row) * 32 + kc * 4 + ldc;
            cp_async16(sbase + 2 * TILE_SW + swz(row, (uint32_t)ldc), Bhi4 + gB);
        }
    };
    auto issueA = [&](int kc) {
        uint32_t sbase = sb + (uint32_t)(kc % 3) * STAGE_SW;
#pragma unroll
        for (int h = 0; h < 2; h++) {
            int row = ldrow + h * 64;
            int rg = block_row + row;
            if (rg >= M) rg = M - 1;
            size_t gA = (size_t)rg * 32 + kc * 4 + ldc;
            uint32_t so = swz(row, (uint32_t)ldc);
            cp_async16(sbase + 0 * TILE_SW + so, Ahi4 + gA);
            cp_async16(sbase + 1 * TILE_SW + so, Alo4 + gA);
        }
    };

    issueB(0);
    issueB(1);
    pdl_wait();
    issueA(0); CP_COMMIT();
    issueA(1); CP_COMMIT();

    for (int kc = 0; kc < 8; kc++) {
        CP_WAIT(1);
        __syncthreads();
        if (kc < 6) { issueA(kc + 2); issueB(kc + 2); CP_COMMIT(); }

        uint32_t base = sb + (uint32_t)(kc % 3) * STAGE_SW;
        uint32_t uAhi = base + 0 * TILE_SW;
        uint32_t uAlo = base + 1 * TILE_SW;
        uint32_t uBhi = base + 2 * TILE_SW;

        uint32_t ah[4][4], al[4][4], bh[2][4];
#pragma unroll
        for (int ks16 = 0; ks16 < 2; ks16++) {
            const uint32_t kb = (uint32_t)(ks16 * 2);
#pragma unroll
            for (int f = 0; f < 4; f++) {
                uint32_t off = a_rowoff[f] + (((a_k0 + kb) ^ a_s[f]) << 4);
                ldsm_x4(uAhi + off, ah[f]);
                ldsm_x4(uAlo + off, al[f]);
            }
#pragma unroll
            for (int p = 0; p < 2; p++) {
                uint32_t off = b_rowoff[p] + (((b_k0 + kb) ^ b_s[p]) << 4);
                ldsm_x4(uBhi + off, bh[p]);
            }
#pragma unroll
            for (int mf = 0; mf < 4; mf++)
#pragma unroll
                for (int nf = 0; nf < 4; nf++) {
                    int p = nf >> 1, q = (nf & 1) * 2;
                    mma16816(acc[mf][nf], ah[mf], bh[p][q], bh[p][q + 1]);
                    mma16816(acc[mf][nf], al[mf], bh[p][q], bh[p][q + 1]);
                }
        }
    }

    pdl_trigger();

    // ---- epilogue ----
#pragma unroll
    for (int mf = 0; mf < 4; mf++) {
        int r0 = block_row + wm * 64 + mf * 16 + (lane >> 2);
        int r1 = r0 + 8;
#pragma unroll
        for (int nf = 0; nf < 4; nf++) {
            int col = block_col + wn * 32 + nf * 8 + (lane & 3) * 2;
            float b0 = bias[col], b1 = bias[col + 1];
            float v00 = fmaxf(acc[mf][nf][0] + b0, 0.f);
            float v01 = fmaxf(acc[mf][nf][1] + b1, 0.f);
            float v10 = fmaxf(acc[mf][nf][2] + b0, 0.f);
            float v11 = fmaxf(acc[mf][nf][3] + b1, 0.f);
            if (mode == 0) {
                if (r0 < M) {
                    *reinterpret_cast<float2*>(&Cf[(size_t)r0 * HID + col]) =
                        make_float2(v00, v01);
                    *reinterpret_cast<float2*>(&Cc[(size_t)r0 * HID + col]) =
                        make_float2(v00, v01);
                }
                if (r1 < M) {
                    *reinterpret_cast<float2*>(&Cf[(size_t)r1 * HID + col]) =
                        make_float2(v10, v11);
                    *reinterpret_cast<float2*>(&Cc[(size_t)r1 * HID + col]) =
                        make_float2(v10, v11);
                }
            } else if (mode == 1) {
                uint32_t hp0 = pack_bf16x2(v00, v01);
                uint32_t hp1 = pack_bf16x2(v10, v11);
                float w00 = v00 - __bfloat162float(__float2bfloat16(v00));
                float w01 = v01 - __bfloat162float(__float2bfloat16(v01));
                float w10 = v10 - __bfloat162float(__float2bfloat16(v10));
                float w11 = v11 - __bfloat162float(__float2bfloat16(v11));
                uint32_t lp0 = pack_bf16x2(w00, w01);
                uint32_t lp1 = pack_bf16x2(w10, w11);
                if (r0 < M) {
                    *reinterpret_cast<uint32_t*>(Chi + (size_t)r0 * HID + col) = hp0;
                    *reinterpret_cast<uint32_t*>(Clo + (size_t)r0 * HID + col) = lp0;
                }
                if (r1 < M) {
                    *reinterpret_cast<uint32_t*>(Chi + (size_t)r1 * HID + col) = hp1;
                    *reinterpret_cast<uint32_t*>(Clo + (size_t)r1 * HID + col) = lp1;
                }
            } else {
                if (r0 < M) {
                    float* pd = pooled + (size_t)batch[r0] * HID + col;
                    atomicAdd(pd + 0, v00);
                    atomicAdd(pd + 1, v01);
                }
                if (r1 < M) {
                    float* pd = pooled + (size_t)batch[r1] * HID + col;
                    atomicAdd(pd + 0, v10);
                    atomicAdd(pd + 1, v11);
                }
            }
        }
    }
}

// ======= GEMM variant 2: fp32 A, in-kernel split, 2-term, 3-stage ===========

#define F_A32_STG 16384
#define F_B_OFF   (3 * F_A32_STG)          // 49152
#define F_B_STG   TILE_SW                   // 8192 (Bhi only)
#define F_AHI     (F_B_OFF + 3 * F_B_STG)  // 73728
#define F_ALO     (F_AHI + TILE_SW)        // 81920
#define F_SMEM    (F_ALO + TILE_SW)        // 90112

__global__ __launch_bounds__(256, 2)
void mma_gemm_split_f32a(int M,
                         const float* __restrict__ Af,
                         const uint4* __restrict__ Bhi4,
                         const float* __restrict__ bias,
                         __nv_bfloat16* __restrict__ Chi,
                         __nv_bfloat16* __restrict__ Clo) {
    extern __shared__ char smem[];
    const uint32_t sb = smem_u32(smem);

    const int tid  = threadIdx.x;
    const int wid  = tid >> 5;
    const int lane = tid & 31;
    const int wm   = wid & 1;
    const int wn   = wid >> 1;
    const int block_col = blockIdx.x * 128;
    const int block_row = blockIdx.y * 128;

    const int a_lrow = lane & 15;
    const int a_lcol = (lane >> 4) << 3;
    const int b_lrow = (lane & 7) + ((lane >> 4) & 1) * 8;
    const int b_lcol = ((lane >> 3) & 1) << 3;
    const uint32_t a_k0 = (uint32_t)(a_lcol >> 3);
    const uint32_t b_k0 = (uint32_t)(b_lcol >> 3);

    uint32_t a_rowoff[4], b_rowoff[2];
    uint32_t a_s[4], b_s[2];
#pragma unroll
    for (int f = 0; f < 4; f++) {
        int r = wm * 64 + f * 16 + a_lrow;
        a_rowoff[f] = (uint32_t)(r * 64);
        a_s[f] = (uint32_t)(r >> 1) & 3u;
    }
#pragma unroll
    for (int p = 0; p < 2; p++) {
        int r = wn * 32 + p * 16 + b_lrow;
        b_rowoff[p] = (uint32_t)(r * 64);
        b_s[p] = (uint32_t)(r >> 1) & 3u;
    }

    float acc[4][4][4];
#pragma unroll
    for (int i = 0; i < 4; i++)
#pragma unroll
        for (int j = 0; j < 4; j++)
#pragma unroll
            for (int c = 0; c < 4; c++) acc[i][j][c] = 0.0f;

    const int ldrow = tid >> 2;
    const int ldc   = tid & 3;
    const int crow  = tid >> 1;
    const int chalf = tid & 1;

    auto issueB = [&](int kc) {
        uint32_t bbase = sb + F_B_OFF + (uint32_t)(kc % 3) * F_B_STG;
#pragma unroll
        for (int h = 0; h < 2; h++) {
            int row = ldrow + h * 64;
            size_t gB = (size_t)(block_col + row) * 32 + kc * 4 + ldc;
            cp_async16(bbase + swz(row, (uint32_t)ldc), Bhi4 + gB);
        }
    };
    auto issueA = [&](int kc) {
        int s = kc % 3;
#pragma unroll
        for (int i = 0; i < 4; i++) {
            int idx = tid + i * 256;
            int row = idx >> 3, c = idx & 7;
            int rg = block_row + row;
            if (rg >= M) rg = M - 1;
            const float* g = Af + (size_t)rg * 256 + kc * 32 + c * 4;
            uint32_t so = (uint32_t)(row * 128) +
                          (((uint32_t)(c ^ (row & 7))) << 4);
            cp_async16(sb + (uint32_t)(s * F_A32_STG) + so, g);
        }
    };

    issueB(0);
    issueB(1);
    pdl_wait();
    issueA(0); CP_COMMIT();
    issueA(1); CP_COMMIT();

    for (int kc = 0; kc < 8; kc++) {
        CP_WAIT(1);
        __syncthreads();
        if (kc < 6) { issueA(kc + 2); issueB(kc + 2); CP_COMMIT(); }

        {
            const char* afb = smem + (kc % 3) * F_A32_STG + crow * 128;
            uint32_t rs = (uint32_t)(crow & 7);
            float4 v0 = *reinterpret_cast<const float4*>(
                afb + (((uint32_t)(chalf * 4 + 0) ^ rs) << 4));
            float4 v1 = *reinterpret_cast<const float4*>(
                afb + (((uint32_t)(chalf * 4 + 1) ^ rs) << 4));
            float4 v2 = *reinterpret_cast<const float4*>(
                afb + (((uint32_t)(chalf * 4 + 2) ^ rs) << 4));
            float4 v3 = *reinterpret_cast<const float4*>(
                afb + (((uint32_t)(chalf * 4 + 3) ^ rs) << 4));
            uint4 H0, H1, L0, L1;
            H0.x = pack_bf16x2(v0.x, v0.y); H0.y = pack_bf16x2(v0.z, v0.w);
            H0.z = pack_bf16x2(v1.x, v1.y); H0.w = pack_bf16x2(v1.z, v1.w);
            H1.x = pack_bf16x2(v2.x, v2.y); H1.y = pack_bf16x2(v2.z, v2.w);
            H1.z = pack_bf16x2(v3.x, v3.y); H1.w = pack_bf16x2(v3.z, v3.w);
            L0.x = pack_bf16x2(v0.x - __bfloat162float(__float2bfloat16(v0.x)),
                               v0.y - __bfloat162float(__float2bfloat16(v0.y)));
            L0.y = pack_bf16x2(v0.z - __bfloat162float(__float2bfloat16(v0.z)),
                               v0.w - __bfloat162float(__float2bfloat16(v0.w)));
            L0.z = pack_bf16x2(v1.x - __bfloat162float(__float2bfloat16(v1.x)),
                               v1.y - __bfloat162float(__float2bfloat16(v1.y)));
            L0.w = pack_bf16x2(v1.z - __bfloat162float(__float2bfloat16(v1.z)),
                               v1.w - __bfloat162float(__float2bfloat16(v1.w)));
            L1.x = pack_bf16x2(v2.x - __bfloat162float(__float2bfloat16(v2.x)),
                               v2.y - __bfloat162float(__float2bfloat16(v2.y)));
            L1.y = pack_bf16x2(v2.z - __bfloat162float(__float2bfloat16(v2.z)),
                               v2.w - __bfloat162float(__float2bfloat16(v2.w)));
            L1.z = pack_bf16x2(v3.x - __bfloat162float(__float2bfloat16(v3.x)),
                               v3.y - __bfloat162float(__float2bfloat16(v3.y)));
            L1.w = pack_bf16x2(v3.z - __bfloat162float(__float2bfloat16(v3.z)),
                               v3.w - __bfloat162float(__float2bfloat16(v3.w)));
            uint32_t cs = (uint32_t)(crow >> 1) & 3u;
            uint32_t g0 = ((uint32_t)(chalf * 2 + 0) ^ cs) << 4;
            uint32_t g1 = ((uint32_t)(chalf * 2 + 1) ^ cs) << 4;
            char* ah = smem + F_AHI + crow * 64;
            char* al = smem + F_ALO + crow * 64;
            *reinterpret_cast<uint4*>(ah + g0) = H0;
            *reinterpret_cast<uint4*>(ah + g1) = H1;
            *reinterpret_cast<uint4*>(al + g0) = L0;
            *reinterpret_cast<uint4*>(al + g1) = L1;
        }
        __syncthreads();

        uint32_t uAhi = sb + F_AHI;
        uint32_t uAlo = sb + F_ALO;
        uint32_t uBhi = sb + F_B_OFF + (uint32_t)(kc % 3) * F_B_STG;

        uint32_t ah[4][4], al[4][4], bh[2][4];
#pragma unroll
        for (int ks16 = 0; ks16 < 2; ks16++) {
            const uint32_t kb = (uint32_t)(ks16 * 2);
#pragma unroll
            for (int f = 0; f < 4; f++) {
                uint32_t off = a_rowoff[f] + (((a_k0 + kb) ^ a_s[f]) << 4);
                ldsm_x4(uAhi + off, ah[f]);
                ldsm_x4(uAlo + off, al[f]);
            }
#pragma unroll
            for (int p = 0; p < 2; p++) {
                uint32_t off = b_rowoff[p] + (((b_k0 + kb) ^ b_s[p]) << 4);
                ldsm_x4(uBhi + off, bh[p]);
            }
#pragma unroll
            for (int mf = 0; mf < 4; mf++)
#pragma unroll
                for (int nf = 0; nf < 4; nf++) {
                    int p = nf >> 1, q = (nf & 1) * 2;
                    mma16816(acc[mf][nf], ah[mf], bh[p][q], bh[p][q + 1]);
                    mma16816(acc[mf][nf], al[mf], bh[p][q], bh[p][q + 1]);
                }
        }
    }

    pdl_trigger();

#pragma unroll
    for (int mf = 0; mf < 4; mf++) {
        int r0 = block_row + wm * 64 + mf * 16 + (lane >> 2);
        int r1 = r0 + 8;
#pragma unroll
        for (int nf = 0; nf < 4; nf++) {
            int col = block_col + wn * 32 + nf * 8 + (lane & 3) * 2;
            float b0 = bias[col], b1 = bias[col + 1];
            float v00 = fmaxf(acc[mf][nf][0] + b0, 0.f);
            float v01 = fmaxf(acc[mf][nf][1] + b1, 0.f);
            float v10 = fmaxf(acc[mf][nf][2] + b0, 0.f);
            float v11 = fmaxf(acc[mf][nf][3] + b1, 0.f);
            uint32_t hp0 = pack_bf16x2(v00, v01);
            uint32_t hp1 = pack_bf16x2(v10, v11);
            float w00 = v00 - __bfloat162float(__float2bfloat16(v00));
            float w01 = v01 - __bfloat162float(__float2bfloat16(v01));
            float w10 = v10 - __bfloat162float(__float2bfloat16(v10));
            float w11 = v11 - __bfloat162float(__float2bfloat16(v11));
            uint32_t lp0 = pack_bf16x2(w00, w01);
            uint32_t lp1 = pack_bf16x2(w10, w11);
            if (r0 < M) {
                *reinterpret_cast<uint32_t*>(Chi + (size_t)r0 * HID + col) = hp0;
                *reinterpret_cast<uint32_t*>(Clo + (size_t)r0 * HID + col) = lp0;
            }
            if (r1 < M) {
                *reinterpret_cast<uint32_t*>(Chi + (size_t)r1 * HID + col) = hp1;
                *reinterpret_cast<uint32_t*>(Clo + (size_t)r1 * HID + col) = lp1;
            }
        }
    }
}

// ====== fp32 tiled SGEMM (head GEMM) with fused mean-divide =================

__global__ __launch_bounds__(256)
void sgemm_bias_relu(int M, const float* __restrict__ A,
                     const float* __restrict__ B,
                     const float* __restrict__ bias,
                     float* __restrict__ C,
                     int N, int K, int doRelu,
                     const float* __restrict__ rowdiv) {
    __shared__ float As[8][128];
    __shared__ float Bs[8][128];

    const int tid       = threadIdx.x;
    const int block_row = blockIdx.y * 128;
    const int block_col = blockIdx.x * 128;

    const int aRow = tid >> 1;
    const int aCol = (tid & 1) << 2;
    const int bRow = tid >> 5;
    const int bCol = (tid & 31) << 2;
    const int trow = (tid >> 4) << 3;
    const int tcol = (tid & 15) << 3;

    float rdiv = 1.0f;
    if (rowdiv && block_row + aRow < M)
        rdiv = 1.0f / fmaxf(rowdiv[block_row + aRow], 1.0f);

    float acc[8][8];
#pragma unroll
    for (int i = 0; i < 8; i++)
#pragma unroll
        for (int j = 0; j < 8; j++) acc[i][j] = 0.0f;

    for (int kt = 0; kt < K; kt += 8) {
        float4 av = make_float4(0.f, 0.f, 0.f, 0.f);
        if (block_row + aRow < M)
            av = *reinterpret_cast<const float4*>(&A[(size_t)(block_row + aRow) * K + kt + aCol]);
        As[aCol + 0][aRow] = av.x * rdiv;
        As[aCol + 1][aRow] = av.y * rdiv;
        As[aCol + 2][aRow] = av.z * rdiv;
        As[aCol + 3][aRow] = av.w * rdiv;

        float4 bv = *reinterpret_cast<const float4*>(&B[(size_t)(kt + bRow) * N + block_col + bCol]);
        *reinterpret_cast<float4*>(&Bs[bRow][bCol]) = bv;
        __syncthreads();

#pragma unroll
        for (int k = 0; k < 8; k++) {
            float ra[8], rb[8];
#pragma unroll
            for (int i = 0; i < 8; i++) ra[i] = As[k][trow + i];
#pragma unroll
            for (int j = 0; j < 8; j++) rb[j] = Bs[k][tcol + j];
#pragma unroll
            for (int i = 0; i < 8; i++)
#pragma unroll
                for (int j = 0; j < 8; j++)
                    acc[i][j] = fmaf(ra[i], rb[j], acc[i][j]);
        }
        __syncthreads();
    }

#pragma unroll
    for (int i = 0; i < 8; i++) {
        int r = block_row + trow + i;
        if (r < M) {
#pragma unroll
            for (int j = 0; j < 8; j += 4) {
                float4 v;
                v.x = acc[i][j + 0] + bias[block_col + tcol + j + 0];
                v.y = acc[i][j + 1] + bias[block_col + tcol + j + 1];
                v.z = acc[i][j + 2] + bias[block_col + tcol + j + 2];
                v.w = acc[i][j + 3] + bias[block_col + tcol + j + 3];
                if (doRelu) {
                    v.x = fmaxf(v.x, 0.f); v.y = fmaxf(v.y, 0.f);
                    v.z = fmaxf(v.z, 0.f); v.w = fmaxf(v.w, 0.f);
                }
                *reinterpret_cast<float4*>(&C[(size_t)r * N + block_col + tcol + j]) = v;
            }
        }
    }
}

// ============================ head final ====================================

__global__ void head_final(const float* __restrict__ hid,
                           const float* __restrict__ W,
                           const float* __restrict__ b,
                           float* __restrict__ out) {
    int m = blockIdx.x * blockDim.x + threadIdx.x;
    if (m >= N_GRAPHS) return;
    float a0 = b[0], a1 = b[1], a2 = b[2];
    const float* hs = hid + (size_t)m * 128;
#pragma unroll 8
    for (int k = 0; k < 128; k++) {
        float h = hs[k];
        a0 = fmaf(h, W[k * 3 + 0], a0);
        a1 = fmaf(h, W[k * 3 + 1], a1);
        a2 = fmaf(h, W[k * 3 + 2], a2);
    }
    out[m * 3 + 0] = a0;
    out[m * 3 + 1] = a1;
    out[m * 3 + 2] = a2;
}

// ============================ launch ========================================

template <typename F, typename... Args>
static void launch_pdl(F* kernel, dim3 grid, dim3 block, size_t smem,
                       Args... args) {
    cudaLaunchConfig_t cfg = {};
    cfg.gridDim = grid;
    cfg.blockDim = block;
    cfg.dynamicSmemBytes = smem;
    cfg.stream = 0;
    cudaLaunchAttribute attr[1];
    attr[0].id = cudaLaunchAttributeProgrammaticStreamSerialization;
    attr[0].val.programmaticStreamSerializationAllowed = 1;
    cfg.attrs = attr;
    cfg.numAttrs = 1;
    cudaLaunchKernelEx(&cfg, kernel, args...);
}

extern "C" void kernel_launch(void* const* d_in, const int* in_sizes, int n_in,
                              void* d_out, int out_size) {
    const float* x     = (const float*)d_in[0];
    const int*   ei    = (const int*)d_in[1];
    const int*   batch = (const int*)d_in[2];

    const float* Wa[4], *ba[4], *Wb[4], *bb[4];
    for (int l = 0; l < 4; l++) {
        Wa[l] = (const float*)d_in[3 + 4 * l + 0];
        ba[l] = (const float*)d_in[3 + 4 * l + 1];
        Wb[l] = (const float*)d_in[3 + 4 * l + 2];
        bb[l] = (const float*)d_in[3 + 4 * l + 3];
    }
    const float* Wh1 = (const float*)d_in[19];
    const float* bh1 = (const float*)d_in[20];
    const float* Wh2 = (const float*)d_in[21];
    const float* bh2 = (const float*)d_in[22];
    float* out = (float*)d_out;

    __nv_bfloat16 *A2hi, *A2lo, *Whi;
    float *bufB, *bufC, *agg7, *pooled, *counts, *hid;
    cudaGetSymbolAddress((void**)&A2hi,   g_A2hi);
    cudaGetSymbolAddress((void**)&A2lo,   g_A2lo);
    cudaGetSymbolAddress((void**)&Whi,    g_Whi);
    cudaGetSymbolAddress((void**)&bufB,   g_bufB);
    cudaGetSymbolAddress((void**)&bufC,   g_bufC);
    cudaGetSymbolAddress((void**)&agg7,   g_agg7);
    cudaGetSymbolAddress((void**)&pooled, g_pooled);
    cudaGetSymbolAddress((void**)&counts, g_counts);
    cudaGetSymbolAddress((void**)&hid,    g_hid);

    cudaFuncSetAttribute(mma_gemm_split,
                         cudaFuncAttributeMaxDynamicSharedMemorySize, GEMM_SMEM);
    cudaFuncSetAttribute(mma_gemm_split_f32a,
                         cudaFuncAttributeMaxDynamicSharedMemorySize, F_SMEM);

    // ---- prologue: weights, counts, pooled init ----
    dim3 cw_grid(HID, 7);
    convert_weight_all<<<cw_grid, HID>>>(Wb[0], Wa[1], Wb[1], Wa[2], Wb[2],
                                         Wa[3], Wb[3], Whi);
    cudaMemsetAsync(pooled, 0, (size_t)N_GRAPHS * HID * sizeof(float));
    cudaMemsetAsync(counts, 0, (size_t)N_GRAPHS * sizeof(float));
    count_kernel<<<(N_NODES + 255) / 256, 256>>>(batch, counts);

    dim3 mma_grid(2, (N_NODES + 127) / 128);
    dim3 sc_grid((unsigned)(((size_t)N_EDGES * 32 + 255) / 256));

    // ---- layer 1 ----
    cudaMemcpyAsync(agg7, x, (size_t)N_NODES * 7 * sizeof(float),
                    cudaMemcpyDeviceToDevice);
    scatter_add_7<<<(N_EDGES + 255) / 256, 256>>>(x, ei, agg7);
    gemm_k7_relu_split<<<K7_BLOCKS, 256>>>(agg7, Wa[0], ba[0], A2hi, A2lo);
    launch_pdl(mma_gemm_split, mma_grid, dim3(256), (size_t)GEMM_SMEM,
               N_NODES, (const uint4*)A2hi, (const uint4*)A2lo,
               (const uint4*)Whi,
               bb[0], bufB, bufC, (__nv_bfloat16*)nullptr,
               (__nv_bfloat16*)nullptr, (const int*)nullptr,
               (float*)nullptr, 0);

    // ---- layers 2..4 ----
    for (int l = 1; l < 4; l++) {
        launch_pdl(scatter_add_256, sc_grid, dim3(256), (size_t)0,
                   (const float*)bufB, ei, bufC);
        launch_pdl(mma_gemm_split_f32a, mma_grid, dim3(256), (size_t)F_SMEM,
                   N_NODES, (const float*)bufC,
                   (const uint4*)(Whi + (size_t)(2 * l - 1) * HID * HID),
                   ba[l], A2hi, A2lo);
        if (l < 3) {
            launch_pdl(mma_gemm_split, mma_grid, dim3(256), (size_t)GEMM_SMEM,
                       N_NODES, (const uint4*)A2hi, (const uint4*)A2lo,
                       (const uint4*)(Whi + (size_t)(2 * l) * HID * HID),
                       bb[l], bufB, bufC, (__nv_bfloat16*)nullptr,
                       (__nv_bfloat16*)nullptr, (const int*)nullptr,
                       (float*)nullptr, 0);
        } else {
            launch_pdl(mma_gemm_split, mma_grid, dim3(256), (size_t)GEMM_SMEM,
                       N_NODES, (const uint4*)A2hi, (const uint4*)A2lo,
                       (const uint4*)(Whi + (size_t)(2 * l) * HID * HID),
                       bb[l], (float*)nullptr, (float*)nullptr,
                       (__nv_bfloat16*)nullptr, (__nv_bfloat16*)nullptr,
                       batch, pooled, 2);
        }
    }

    // ---- head (mean-divide fused into A load) ----
    dim3 head_grid(1, (N_GRAPHS + 127) / 128);
    sgemm_bias_relu<<<head_grid, 256>>>(N_GRAPHS, pooled, Wh1, bh1, hid,
                                        128, 256, 1, counts);
    head_final<<<(N_GRAPHS + 255) / 256, 256>>>(hid, Wh2, bh2, out);
}